// round 1
// baseline (speedup 1.0000x reference)
#include <cuda_runtime.h>
#include <math.h>

#define B_ 8192
#define D_ 1024
#define L_ 5
#define H_ 512
#define BD_ (B_ * D_)

// ---------------- scratch (device globals; no allocations) ----------------
__device__ float g_cur[B_ * D_];
__device__ float g_buf2d[B_ * 2 * D_];
__device__ float g_pat[B_ * D_];
__device__ float g_tmp[B_ * D_];       // reused: es pre-LN [B,D], qg1 pre-LN [B,H]
__device__ float g_emo[B_ * D_];       // emo accumulator
__device__ float g_psum[B_ * D_];      // sum of stable over layers
__device__ float g_psq[B_ * D_];       // sum of stable^2
__device__ float g_cmat[D_ * D_];      // coherence matrix
__device__ double g_part[1024];        // reduction partials

// ---------------- GEMM: C = act(A[MxK] @ W[KxN] + bias) ----------------
#define BM 128
#define BN 128
#define BK 16

enum { ACT_NONE = 0, ACT_TANH_STABLE = 1, ACT_SIGMOID = 2 };

__global__ void __launch_bounds__(256, 2) gemm_kernel(
    const float* __restrict__ A, const float* __restrict__ W,
    const float* __restrict__ bias, float* __restrict__ C,
    int N, int K, int act,
    const float* __restrict__ sc,      // stability controllers (row [D])
    float* __restrict__ curout,        // stable -> next layer input
    float* __restrict__ psum, float* __restrict__ psq)
{
    __shared__ float As[BK][BM + 4];
    __shared__ float Ws[BK][BN];

    const int tid = threadIdx.x;
    const int tx = tid & 15;
    const int ty = tid >> 4;
    const int rowBase = blockIdx.y * BM;
    const int colBase = blockIdx.x * BN;

    float acc[8][8];
#pragma unroll
    for (int i = 0; i < 8; i++)
#pragma unroll
        for (int j = 0; j < 8; j++) acc[i][j] = 0.f;

    for (int kt = 0; kt < K; kt += BK) {
#pragma unroll
        for (int s = 0; s < 2; s++) {
            int f = tid + s * 256;          // 512 float4 total
            int r = f >> 2;                 // 0..127
            int c4 = (f & 3) << 2;          // 0,4,8,12
            float4 v = *(const float4*)(A + (size_t)(rowBase + r) * K + kt + c4);
            As[c4 + 0][r] = v.x;
            As[c4 + 1][r] = v.y;
            As[c4 + 2][r] = v.z;
            As[c4 + 3][r] = v.w;
        }
#pragma unroll
        for (int s = 0; s < 2; s++) {
            int f = tid + s * 256;
            int r = f >> 5;                 // 0..15
            int c4 = (f & 31) << 2;         // 0..124
            float4 v = *(const float4*)(W + (size_t)(kt + r) * N + colBase + c4);
            *(float4*)&Ws[r][c4] = v;
        }
        __syncthreads();

#pragma unroll
        for (int k = 0; k < BK; k++) {
            float a[8], b[8];
            *(float4*)&a[0] = *(const float4*)&As[k][ty * 8];
            *(float4*)&a[4] = *(const float4*)&As[k][ty * 8 + 4];
            *(float4*)&b[0] = *(const float4*)&Ws[k][tx * 8];
            *(float4*)&b[4] = *(const float4*)&Ws[k][tx * 8 + 4];
#pragma unroll
            for (int i = 0; i < 8; i++)
#pragma unroll
                for (int j = 0; j < 8; j++) acc[i][j] += a[i] * b[j];
        }
        __syncthreads();
    }

    // epilogue (scalar stores: anchor output is offset by +1 element, not 16B aligned)
#pragma unroll
    for (int i = 0; i < 8; i++) {
        int row = rowBase + ty * 8 + i;
#pragma unroll
        for (int j = 0; j < 8; j++) {
            int col = colBase + tx * 8 + j;
            float v = acc[i][j] + (bias ? bias[col] : 0.f);
            size_t idx = (size_t)row * N + col;
            if (act == ACT_NONE) {
                C[idx] = v;
            } else if (act == ACT_SIGMOID) {
                C[idx] = 1.f / (1.f + expf(-v));
            } else { // ACT_TANH_STABLE
                float p = tanhf(v);
                C[idx] = p;
                float s = p * (1.f / (1.f + expf(-sc[col])));
                curout[idx] = s;
                psum[idx] += s;
                psq[idx] += s * s;
            }
        }
    }
}

// ---------------- LayerNorm + activation (one block per row) ----------------
// act: 0 = GELU(exact) -> out, 1 = sigmoid -> accum +=, 2 = ReLU -> out
__global__ void __launch_bounds__(256) ln_act_kernel(
    const float* __restrict__ in, const float* __restrict__ g,
    const float* __restrict__ be, float* __restrict__ out,
    float* __restrict__ accum, int N, int act)
{
    const int row = blockIdx.x;
    const float* x = in + (size_t)row * N;
    const int per = N >> 8;              // N/256 in {2,4,8}
    float vals[8];
    float s = 0.f, ss = 0.f;
    for (int t = 0; t < per; t++) {
        float v = x[threadIdx.x + (t << 8)];
        vals[t] = v;
        s += v;
        ss += v * v;
    }
#pragma unroll
    for (int o = 16; o > 0; o >>= 1) {
        s += __shfl_down_sync(0xffffffff, s, o);
        ss += __shfl_down_sync(0xffffffff, ss, o);
    }
    __shared__ float sm[16];
    __shared__ float s_mean, s_rstd;
    const int w = threadIdx.x >> 5, lane = threadIdx.x & 31;
    if (lane == 0) { sm[w] = s; sm[8 + w] = ss; }
    __syncthreads();
    if (threadIdx.x == 0) {
        float S = 0.f, SS = 0.f;
        for (int i = 0; i < 8; i++) { S += sm[i]; SS += sm[8 + i]; }
        float m = S / (float)N;
        float var = SS / (float)N - m * m;
        s_mean = m;
        s_rstd = rsqrtf(var + 1e-5f);
    }
    __syncthreads();
    const float m = s_mean, r = s_rstd;
    for (int t = 0; t < per; t++) {
        int c = threadIdx.x + (t << 8);
        float v = (vals[t] - m) * r * g[c] + be[c];
        size_t idx = (size_t)row * N + c;
        if (act == 0) {
            out[idx] = 0.5f * v * (1.f + erff(v * 0.70710678118654752f));
        } else if (act == 1) {
            accum[idx] += 1.f / (1.f + expf(-v));
        } else {
            out[idx] = fmaxf(v, 0.f);
        }
    }
}

// ---------------- small helpers ----------------
__global__ void __launch_bounds__(256) zero3_kernel(float* a, float* b, float* c, int n) {
    for (int i = blockIdx.x * 256 + threadIdx.x; i < n; i += gridDim.x * 256) {
        a[i] = 0.f; b[i] = 0.f; c[i] = 0.f;
    }
}

__global__ void __launch_bounds__(256) cinit_kernel(float* C) {
    int idx = blockIdx.x * 256 + threadIdx.x;
    int k = idx >> 10;           // / D_
    int j = idx & (D_ - 1);
    int e = (j - k + D_) & (D_ - 1);   // (j-k) mod D (D power of 2)
    C[idx] = powf(0.9f, (float)e);
}

__global__ void __launch_bounds__(256) finalize_kernel(
    const float* __restrict__ ps, const float* __restrict__ es, float* __restrict__ out) {
    for (int i = blockIdx.x * 256 + threadIdx.x; i < BD_; i += gridDim.x * 256) {
        out[i] = ps[i] * 0.2f;
        out[(size_t)BD_ + i] = es[i] * 0.2f;
    }
}

__global__ void __launch_bounds__(256) stab_part_kernel(
    const float* __restrict__ ps, const float* __restrict__ psq, double* __restrict__ part) {
    double acc = 0.0;
    for (int i = blockIdx.x * 256 + threadIdx.x; i < BD_; i += gridDim.x * 256) {
        float s = ps[i], q = psq[i];
        acc += (double)((q - s * s * 0.2f) * 0.25f);   // unbiased var over L=5
    }
#pragma unroll
    for (int o = 16; o > 0; o >>= 1)
        acc += __shfl_down_sync(0xffffffff, acc, o);
    __shared__ double sm[8];
    int w = threadIdx.x >> 5, lane = threadIdx.x & 31;
    if (lane == 0) sm[w] = acc;
    __syncthreads();
    if (threadIdx.x == 0) {
        double t = 0.0;
        for (int i = 0; i < 8; i++) t += sm[i];
        part[blockIdx.x] = t;
    }
}

__global__ void __launch_bounds__(256) stab_final_kernel(const double* __restrict__ part,
                                                         float* __restrict__ out) {
    double acc = 0.0;
    for (int i = threadIdx.x; i < 1024; i += 256) acc += part[i];
#pragma unroll
    for (int o = 16; o > 0; o >>= 1)
        acc += __shfl_down_sync(0xffffffff, acc, o);
    __shared__ double sm[8];
    int w = threadIdx.x >> 5, lane = threadIdx.x & 31;
    if (lane == 0) sm[w] = acc;
    __syncthreads();
    if (threadIdx.x == 0) {
        double t = 0.0;
        for (int i = 0; i < 8; i++) t += sm[i];
        out[0] = (float)(1.0 - t / (double)BD_);
    }
}

// ---------------- host launch ----------------
extern "C" void kernel_launch(void* const* d_in, const int* in_sizes, int n_in,
                              void* d_out, int out_size)
{
    // Input layout: detect whether target_layer (scalar) sits at index 1
    // (setup_inputs dict order) or was placed last / dropped (signature order).
    const float* seed = (const float*)d_in[0];
    const int o = (in_sizes[1] == 1) ? 2 : 1;
    const float* pg_w1 = (const float*)d_in[o + 0];
    const float* pg_b1 = (const float*)d_in[o + 1];
    const float* pg_g1 = (const float*)d_in[o + 2];
    const float* pg_be1 = (const float*)d_in[o + 3];
    const float* pg_w2 = (const float*)d_in[o + 4];
    const float* pg_b2 = (const float*)d_in[o + 5];
    const float* es_w = (const float*)d_in[o + 6];
    const float* es_b = (const float*)d_in[o + 7];
    const float* es_g = (const float*)d_in[o + 8];
    const float* es_be = (const float*)d_in[o + 9];
    const float* qg_w1 = (const float*)d_in[o + 10];
    const float* qg_b1 = (const float*)d_in[o + 11];
    const float* qg_g1 = (const float*)d_in[o + 12];
    const float* qg_be1 = (const float*)d_in[o + 13];
    const float* qg_w2 = (const float*)d_in[o + 14];
    const float* qg_b2 = (const float*)d_in[o + 15];
    const float* sc = (const float*)d_in[o + 16];
    float* out = (float*)d_out;

    float *cur, *buf2d, *pat, *tmp, *emo, *psum, *psq, *cmat;
    double* part;
    cudaGetSymbolAddress((void**)&cur, g_cur);
    cudaGetSymbolAddress((void**)&buf2d, g_buf2d);
    cudaGetSymbolAddress((void**)&pat, g_pat);
    cudaGetSymbolAddress((void**)&tmp, g_tmp);
    cudaGetSymbolAddress((void**)&emo, g_emo);
    cudaGetSymbolAddress((void**)&psum, g_psum);
    cudaGetSymbolAddress((void**)&psq, g_psq);
    cudaGetSymbolAddress((void**)&cmat, g_cmat);
    cudaGetSymbolAddress((void**)&part, g_part);

    const size_t BD = (size_t)BD_;
    float* out_cp = out;                       // combined_pattern  [B,D]
    float* out_ce = out + BD;                  // combined_emotional[B,D]
    float* out_cf = out + 2 * BD;              // coherence_field   [B,D]
    float* out_ss = out + 3 * BD;              // stability_score   scalar
    float* out_qa = out + 3 * BD + 1;          // quantum_anchors   [L,B,D]

    zero3_kernel<<<4096, 256>>>(psum, psq, emo, BD_);
    cudaMemcpyAsync(cur, seed, BD * sizeof(float), cudaMemcpyDeviceToDevice);
    cinit_kernel<<<(D_ * D_) / 256, 256>>>(cmat);

    const dim3 gridN2D(2 * D_ / BN, B_ / BM);  // N=2048
    const dim3 gridND(D_ / BN, B_ / BM);       // N=1024
    const dim3 gridNH(H_ / BN, B_ / BM);       // N=512

    for (int l = 0; l < L_; l++) {
        // 1) pre1 = cur @ pg_w1 + b1   [B,2D]
        gemm_kernel<<<gridN2D, 256>>>(cur, pg_w1 + (size_t)l * D_ * 2 * D_,
                                      pg_b1 + (size_t)l * 2 * D_, buf2d,
                                      2 * D_, D_, ACT_NONE, nullptr, nullptr, nullptr, nullptr);
        // 2) h = GELU(LN(pre1)) in place
        ln_act_kernel<<<B_, 256>>>(buf2d, pg_g1 + (size_t)l * 2 * D_,
                                   pg_be1 + (size_t)l * 2 * D_, buf2d, nullptr, 2 * D_, 0);
        // 3) pat = tanh(h @ pg_w2 + b2); fused stable/cur/sum/sumsq
        gemm_kernel<<<gridND, 256>>>(buf2d, pg_w2 + (size_t)l * 2 * D_ * D_,
                                     pg_b2 + (size_t)l * D_, pat,
                                     D_, 2 * D_, ACT_TANH_STABLE,
                                     sc + (size_t)l * D_, cur, psum, psq);
        // 4) es pre-LN = pat @ es_w + es_b
        gemm_kernel<<<gridND, 256>>>(pat, es_w + (size_t)l * D_ * D_,
                                     es_b + (size_t)l * D_, tmp,
                                     D_, D_, ACT_NONE, nullptr, nullptr, nullptr, nullptr);
        // 5) emo += sigmoid(LN(.))
        ln_act_kernel<<<B_, 256>>>(tmp, es_g + (size_t)l * D_,
                                   es_be + (size_t)l * D_, nullptr, emo, D_, 1);
        // 6) q pre-LN = pat @ qg_w1 + b   [B,H]
        gemm_kernel<<<gridNH, 256>>>(pat, qg_w1 + (size_t)l * D_ * H_,
                                     qg_b1 + (size_t)l * H_, tmp,
                                     H_, D_, ACT_NONE, nullptr, nullptr, nullptr, nullptr);
        // 7) ReLU(LN(.)) in place
        ln_act_kernel<<<B_, 256>>>(tmp, qg_g1 + (size_t)l * H_,
                                   qg_be1 + (size_t)l * H_, tmp, nullptr, H_, 2);
        // 8) anchors[l] = . @ qg_w2 + b2  -> directly into d_out
        gemm_kernel<<<gridND, 256>>>(tmp, qg_w2 + (size_t)l * H_ * D_,
                                     qg_b2 + (size_t)l * D_, out_qa + (size_t)l * BD,
                                     D_, H_, ACT_NONE, nullptr, nullptr, nullptr, nullptr);
    }

    // combined_pattern / combined_emotional (means over L=5)
    finalize_kernel<<<4096, 256>>>(psum, emo, out);
    // coherence_field = sigmoid(combined_pattern @ C)
    gemm_kernel<<<gridND, 256>>>(out_cp, cmat, nullptr, out_cf,
                                 D_, D_, ACT_SIGMOID, nullptr, nullptr, nullptr, nullptr);
    // stability_score
    stab_part_kernel<<<1024, 256>>>(psum, psq, part);
    stab_final_kernel<<<1, 256>>>(part, out_ss);
    (void)n_in; (void)out_size; (void)out_ce;
}

// round 3
// speedup vs baseline: 2.8801x; 2.8801x over previous
#include <cuda_runtime.h>
#include <math.h>
#include <stdint.h>

#define B_ 8192
#define D_ 1024
#define L_ 5
#define H_ 512
#define BD_ (B_ * D_)

// ================= scratch (device globals; no allocations) =================
__device__ float g_cur[B_ * D_];
__device__ float g_buf2d[B_ * 2 * D_];
__device__ float g_pat[B_ * D_];
__device__ float g_tmp[B_ * D_];
__device__ float g_emo[B_ * D_];
__device__ float g_psum[B_ * D_];
__device__ float g_psq[B_ * D_];
__device__ float g_cmat[D_ * D_];            // C[k][n] = 0.9^((n-k)%D), tf32-rounded
__device__ double g_part[1024];
// tf32-rounded weights (same [K,N] layout as inputs)
__device__ float g_wpg1[L_ * D_ * 2 * D_];
__device__ float g_wpg2[L_ * 2 * D_ * D_];
__device__ float g_wes [L_ * D_ * D_];
__device__ float g_wqg1[L_ * D_ * H_];
__device__ float g_wqg2[L_ * H_ * D_];

enum { ACT_NONE = 0, ACT_TANH_STABLE = 1, ACT_SIGMOID = 2 };

// ================= helpers =================
__device__ __forceinline__ float rna_tf32(float x) {
    float r;
    asm("cvt.rna.tf32.f32 %0, %1;" : "=f"(r) : "f"(x));
    return r;
}
__device__ __forceinline__ uint32_t smem_u32(const void* p) {
    uint32_t a;
    asm("{ .reg .u64 t; cvta.to.shared.u64 t, %1; cvt.u32.u64 %0, t; }"
        : "=r"(a) : "l"(p));
    return a;
}
__device__ __forceinline__ void cp16(uint32_t dst, const void* src) {
    asm volatile("cp.async.cg.shared.global [%0], [%1], 16;" :: "r"(dst), "l"(src));
}
__device__ __forceinline__ void cp_commit() {
    asm volatile("cp.async.commit_group;" ::: "memory");
}
template <int N>
__device__ __forceinline__ void cp_wait() {
    asm volatile("cp.async.wait_group %0;" :: "n"(N) : "memory");
}
__device__ __forceinline__ void mma_tf32(float* d, const uint32_t* a, const uint32_t* b) {
    asm volatile(
        "mma.sync.aligned.m16n8k8.row.col.f32.tf32.tf32.f32 "
        "{%0,%1,%2,%3}, {%4,%5,%6,%7}, {%8,%9}, {%0,%1,%2,%3};"
        : "+f"(d[0]), "+f"(d[1]), "+f"(d[2]), "+f"(d[3])
        : "r"(a[0]), "r"(a[1]), "r"(a[2]), "r"(a[3]), "r"(b[0]), "r"(b[1]));
}

// ================= tf32 tensor-core GEMM =================
// C[M,N] = act(A[M,K] @ W[K,N] + bias). A tf32-rounded [M,K] row-major,
// W tf32-rounded [K,N] row-major (acts as col-major B for mma row.col).
#define MT 128
#define NT 128
#define KC 32
#define STAGES 3
#define A_STRIDE 36                        // floats per A smem row (pad, conflict-free)
#define B_STRIDE 136                       // floats per B smem row (pad, conflict-free)
#define A_FLOATS (MT * A_STRIDE)           // 4608
#define B_FLOATS (KC * B_STRIDE)           // 4352
#define STAGE_FLOATS (A_FLOATS + B_FLOATS) // 8960
#define GEMM_SMEM (STAGES * STAGE_FLOATS * 4)  // 107520 bytes

__device__ __forceinline__ void copy_tiles(
    const float* __restrict__ A, const float* __restrict__ W, int N, int K,
    int rowBase, int colBase, int k0, uint32_t stageAddr, int tid)
{
    // A tile: 128 rows x 32 floats (8 x 16B per row) => 1024 cp16, 4/thread
#pragma unroll
    for (int j = 0; j < 4; j++) {
        int idx = tid + j * 256;
        int r = idx >> 3, c = idx & 7;
        const float* src = A + (size_t)(rowBase + r) * K + k0 + c * 4;
        cp16(stageAddr + (uint32_t)(r * A_STRIDE * 4 + c * 16), src);
    }
    // B tile: 32 k-rows x 128 floats (32 x 16B per row) => 1024 cp16, 4/thread
    const uint32_t bAddr = stageAddr + A_FLOATS * 4;
#pragma unroll
    for (int j = 0; j < 4; j++) {
        int idx = tid + j * 256;
        int kr = idx >> 5, c = idx & 31;
        const float* src = W + (size_t)(k0 + kr) * N + colBase + c * 4;
        cp16(bAddr + (uint32_t)(kr * B_STRIDE * 4 + c * 16), src);
    }
}

__global__ void __launch_bounds__(256, 2) mma_gemm(
    const float* __restrict__ A, const float* __restrict__ W,
    const float* __restrict__ bias, float* __restrict__ C,
    int N, int K, int act,
    const float* __restrict__ sc, float* __restrict__ curout,
    float* __restrict__ psum, float* __restrict__ psq)
{
    extern __shared__ float sm[];
    const uint32_t sb = smem_u32(sm);
    const int tid = threadIdx.x;
    const int wid = tid >> 5, lane = tid & 31;
    const int g = lane >> 2, tig = lane & 3;       // mma group / thread-in-group
    const int warp_m = wid & 1;                    // 0..1  (64 rows each)
    const int warp_n = wid >> 1;                   // 0..3  (32 cols each)
    const int rowBase = blockIdx.y * MT;
    const int colBase = blockIdx.x * NT;
    const int nk = K / KC;

    float acc[4][4][4];
#pragma unroll
    for (int mi = 0; mi < 4; mi++)
#pragma unroll
        for (int ni = 0; ni < 4; ni++)
#pragma unroll
            for (int q = 0; q < 4; q++) acc[mi][ni][q] = 0.f;

    // prologue: stage first STAGES-1 chunks
#pragma unroll
    for (int s = 0; s < STAGES - 1; s++) {
        copy_tiles(A, W, N, K, rowBase, colBase, s * KC,
                   sb + (uint32_t)(s * STAGE_FLOATS * 4), tid);
        cp_commit();
    }

    for (int i = 0; i < nk; i++) {
        if (i < nk - 1) cp_wait<1>(); else cp_wait<0>();
        __syncthreads();

        // prefetch chunk i+STAGES-1 into slot (i+STAGES-1)%STAGES
        if (i + STAGES - 1 < nk) {
            int s = (i + STAGES - 1) % STAGES;
            copy_tiles(A, W, N, K, rowBase, colBase, (i + STAGES - 1) * KC,
                       sb + (uint32_t)(s * STAGE_FLOATS * 4), tid);
            cp_commit();
        }

        // compute on slot i%STAGES
        const float* As = sm + (i % STAGES) * STAGE_FLOATS;
        const float* Bs = As + A_FLOATS;
        const int arow0 = warp_m * 64;
        const int bcol0 = warp_n * 32;

#pragma unroll
        for (int ks = 0; ks < 4; ks++) {
            const int k0 = ks * 8;
            uint32_t af[4][4], bf[4][2];
#pragma unroll
            for (int mi = 0; mi < 4; mi++) {
                const float* ap = As + (arow0 + mi * 16 + g) * A_STRIDE + k0 + tig;
                af[mi][0] = __float_as_uint(ap[0]);
                af[mi][1] = __float_as_uint(ap[8 * A_STRIDE]);
                af[mi][2] = __float_as_uint(ap[4]);
                af[mi][3] = __float_as_uint(ap[8 * A_STRIDE + 4]);
            }
#pragma unroll
            for (int ni = 0; ni < 4; ni++) {
                const float* bp = Bs + (k0 + tig) * B_STRIDE + bcol0 + ni * 8 + g;
                bf[ni][0] = __float_as_uint(bp[0]);
                bf[ni][1] = __float_as_uint(bp[4 * B_STRIDE]);
            }
#pragma unroll
            for (int mi = 0; mi < 4; mi++)
#pragma unroll
                for (int ni = 0; ni < 4; ni++)
                    mma_tf32(acc[mi][ni], af[mi], bf[ni]);
        }
        __syncthreads();
    }

    // ---------------- fused epilogue ----------------
#pragma unroll
    for (int mi = 0; mi < 4; mi++) {
        const int r0 = rowBase + warp_m * 64 + mi * 16 + g;
#pragma unroll
        for (int ni = 0; ni < 4; ni++) {
            const int c0 = colBase + warp_n * 32 + ni * 8 + tig * 2;
#pragma unroll
            for (int q = 0; q < 4; q++) {
                const int row = r0 + (q >> 1) * 8;
                const int col = c0 + (q & 1);
                float v = acc[mi][ni][q];
                size_t idx = (size_t)row * N + col;
                if (act == ACT_NONE) {
                    C[idx] = v + bias[col];
                } else if (act == ACT_SIGMOID) {
                    C[idx] = 1.f / (1.f + expf(-v));
                } else {  // ACT_TANH_STABLE
                    v += bias[col];
                    float p = tanhf(v);
                    float s = p * (1.f / (1.f + expf(-sc[col])));
                    C[idx] = rna_tf32(p);        // pat: GEMM input -> rounded
                    curout[idx] = rna_tf32(s);   // next-layer GEMM input -> rounded
                    psum[idx] += s;              // output path: full fp32
                    psq[idx] += s * s;
                }
            }
        }
    }
}

// ================= LayerNorm + activation =================
// act: 0 = GELU(exact)->out (tf32-rounded), 1 = sigmoid->accum+=, 2 = ReLU->out (rounded)
__global__ void __launch_bounds__(256) ln_act_kernel(
    const float* __restrict__ in, const float* __restrict__ g,
    const float* __restrict__ be, float* __restrict__ out,
    float* __restrict__ accum, int N, int act)
{
    const int row = blockIdx.x;
    const float* x = in + (size_t)row * N;
    const int per = N >> 8;
    float vals[8];
    float s = 0.f, ss = 0.f;
    for (int t = 0; t < per; t++) {
        float v = x[threadIdx.x + (t << 8)];
        vals[t] = v;
        s += v;
        ss += v * v;
    }
#pragma unroll
    for (int o = 16; o > 0; o >>= 1) {
        s += __shfl_down_sync(0xffffffff, s, o);
        ss += __shfl_down_sync(0xffffffff, ss, o);
    }
    __shared__ float sm[16];
    __shared__ float s_mean, s_rstd;
    const int w = threadIdx.x >> 5, lane = threadIdx.x & 31;
    if (lane == 0) { sm[w] = s; sm[8 + w] = ss; }
    __syncthreads();
    if (threadIdx.x == 0) {
        float S = 0.f, SS = 0.f;
        for (int i = 0; i < 8; i++) { S += sm[i]; SS += sm[8 + i]; }
        float m = S / (float)N;
        float var = SS / (float)N - m * m;
        s_mean = m;
        s_rstd = rsqrtf(var + 1e-5f);
    }
    __syncthreads();
    const float m = s_mean, r = s_rstd;
    for (int t = 0; t < per; t++) {
        int c = threadIdx.x + (t << 8);
        float v = (vals[t] - m) * r * g[c] + be[c];
        size_t idx = (size_t)row * N + c;
        if (act == 0) {
            out[idx] = rna_tf32(0.5f * v * (1.f + erff(v * 0.70710678118654752f)));
        } else if (act == 1) {
            accum[idx] += 1.f / (1.f + expf(-v));
        } else {
            out[idx] = rna_tf32(fmaxf(v, 0.f));
        }
    }
}

// ================= small kernels =================
__global__ void __launch_bounds__(256) zero3_kernel(float* a, float* b, float* c, int n) {
    for (int i = blockIdx.x * 256 + threadIdx.x; i < n; i += gridDim.x * 256) {
        a[i] = 0.f; b[i] = 0.f; c[i] = 0.f;
    }
}

__global__ void __launch_bounds__(256) rna_copy_kernel(const float* __restrict__ in,
                                                       float* __restrict__ out, int n) {
    for (int i = blockIdx.x * 256 + threadIdx.x; i < n; i += gridDim.x * 256)
        out[i] = rna_tf32(in[i]);
}

// C[k][n] = 0.9^((n-k) mod D), tf32-rounded
__global__ void __launch_bounds__(256) cinit_kernel(float* C) {
    int idx = blockIdx.x * 256 + threadIdx.x;
    int k = idx >> 10;
    int n = idx & (D_ - 1);
    int e = (n - k + D_) & (D_ - 1);
    C[idx] = rna_tf32(powf(0.9f, (float)e));
}

__global__ void __launch_bounds__(256) finalize_kernel(
    const float* __restrict__ ps, const float* __restrict__ es,
    float* __restrict__ out, float* __restrict__ rcp) {
    for (int i = blockIdx.x * 256 + threadIdx.x; i < BD_; i += gridDim.x * 256) {
        float cp = ps[i] * 0.2f;
        out[i] = cp;
        out[(size_t)BD_ + i] = es[i] * 0.2f;
        rcp[i] = rna_tf32(cp);
    }
}

__global__ void __launch_bounds__(256) stab_part_kernel(
    const float* __restrict__ ps, const float* __restrict__ psq, double* __restrict__ part) {
    double acc = 0.0;
    for (int i = blockIdx.x * 256 + threadIdx.x; i < BD_; i += gridDim.x * 256) {
        float s = ps[i], q = psq[i];
        acc += (double)((q - s * s * 0.2f) * 0.25f);
    }
#pragma unroll
    for (int o = 16; o > 0; o >>= 1)
        acc += __shfl_down_sync(0xffffffff, acc, o);
    __shared__ double sm[8];
    int w = threadIdx.x >> 5, lane = threadIdx.x & 31;
    if (lane == 0) sm[w] = acc;
    __syncthreads();
    if (threadIdx.x == 0) {
        double t = 0.0;
        for (int i = 0; i < 8; i++) t += sm[i];
        part[blockIdx.x] = t;
    }
}

__global__ void __launch_bounds__(256) stab_final_kernel(const double* __restrict__ part,
                                                         float* __restrict__ out) {
    double acc = 0.0;
    for (int i = threadIdx.x; i < 1024; i += 256) acc += part[i];
#pragma unroll
    for (int o = 16; o > 0; o >>= 1)
        acc += __shfl_down_sync(0xffffffff, acc, o);
    __shared__ double sm[8];
    int w = threadIdx.x >> 5, lane = threadIdx.x & 31;
    if (lane == 0) sm[w] = acc;
    __syncthreads();
    if (threadIdx.x == 0) {
        double t = 0.0;
        for (int i = 0; i < 8; i++) t += sm[i];
        out[0] = (float)(1.0 - t / (double)BD_);
    }
}

// ================= host launch =================
static inline void launch_gemm(const float* A, const float* W, const float* bias,
                               float* C, int N, int K, int act,
                               const float* sc, float* curout, float* psum, float* psq) {
    dim3 grid(N / NT, B_ / MT);
    mma_gemm<<<grid, 256, GEMM_SMEM>>>(A, W, bias, C, N, K, act, sc, curout, psum, psq);
}

extern "C" void kernel_launch(void* const* d_in, const int* in_sizes, int n_in,
                              void* d_out, int out_size)
{
    const float* seed = (const float*)d_in[0];
    const int o = (in_sizes[1] == 1) ? 2 : 1;
    const float* pg_w1 = (const float*)d_in[o + 0];
    const float* pg_b1 = (const float*)d_in[o + 1];
    const float* pg_g1 = (const float*)d_in[o + 2];
    const float* pg_be1 = (const float*)d_in[o + 3];
    const float* pg_w2 = (const float*)d_in[o + 4];
    const float* pg_b2 = (const float*)d_in[o + 5];
    const float* es_w = (const float*)d_in[o + 6];
    const float* es_b = (const float*)d_in[o + 7];
    const float* es_g = (const float*)d_in[o + 8];
    const float* es_be = (const float*)d_in[o + 9];
    const float* qg_w1 = (const float*)d_in[o + 10];
    const float* qg_b1 = (const float*)d_in[o + 11];
    const float* qg_g1 = (const float*)d_in[o + 12];
    const float* qg_be1 = (const float*)d_in[o + 13];
    const float* qg_w2 = (const float*)d_in[o + 14];
    const float* qg_b2 = (const float*)d_in[o + 15];
    const float* sc = (const float*)d_in[o + 16];
    float* out = (float*)d_out;

    float *cur, *buf2d, *pat, *tmp, *emo, *psum, *psq, *cmat;
    float *wpg1, *wpg2, *wes, *wqg1, *wqg2;
    double* part;
    cudaGetSymbolAddress((void**)&cur, g_cur);
    cudaGetSymbolAddress((void**)&buf2d, g_buf2d);
    cudaGetSymbolAddress((void**)&pat, g_pat);
    cudaGetSymbolAddress((void**)&tmp, g_tmp);
    cudaGetSymbolAddress((void**)&emo, g_emo);
    cudaGetSymbolAddress((void**)&psum, g_psum);
    cudaGetSymbolAddress((void**)&psq, g_psq);
    cudaGetSymbolAddress((void**)&cmat, g_cmat);
    cudaGetSymbolAddress((void**)&part, g_part);
    cudaGetSymbolAddress((void**)&wpg1, g_wpg1);
    cudaGetSymbolAddress((void**)&wpg2, g_wpg2);
    cudaGetSymbolAddress((void**)&wes, g_wes);
    cudaGetSymbolAddress((void**)&wqg1, g_wqg1);
    cudaGetSymbolAddress((void**)&wqg2, g_wqg2);

    cudaFuncSetAttribute(mma_gemm, cudaFuncAttributeMaxDynamicSharedMemorySize, GEMM_SMEM);

    const size_t BD = (size_t)BD_;
    float* out_cf = out + 2 * BD;
    float* out_ss = out + 3 * BD;
    float* out_qa = out + 3 * BD + 1;

    zero3_kernel<<<4096, 256>>>(psum, psq, emo, BD_);
    rna_copy_kernel<<<4096, 256>>>(seed, cur, BD_);
    cinit_kernel<<<(D_ * D_) / 256, 256>>>(cmat);

    // tf32-round all weights (layout unchanged)
    rna_copy_kernel<<<8192, 256>>>(pg_w1, wpg1, L_ * D_ * 2 * D_);
    rna_copy_kernel<<<8192, 256>>>(pg_w2, wpg2, L_ * 2 * D_ * D_);
    rna_copy_kernel<<<4096, 256>>>(es_w, wes, L_ * D_ * D_);
    rna_copy_kernel<<<2048, 256>>>(qg_w1, wqg1, L_ * D_ * H_);
    rna_copy_kernel<<<2048, 256>>>(qg_w2, wqg2, L_ * H_ * D_);

    for (int l = 0; l < L_; l++) {
        // 1) pre1 = cur @ pg_w1 + b1   [B,2D]
        launch_gemm(cur, wpg1 + (size_t)l * D_ * 2 * D_, pg_b1 + (size_t)l * 2 * D_,
                    buf2d, 2 * D_, D_, ACT_NONE, nullptr, nullptr, nullptr, nullptr);
        // 2) h = GELU(LN(pre1))
        ln_act_kernel<<<B_, 256>>>(buf2d, pg_g1 + (size_t)l * 2 * D_,
                                   pg_be1 + (size_t)l * 2 * D_, buf2d, nullptr, 2 * D_, 0);
        // 3) pat = tanh(h @ pg_w2 + b2); fused stable/cur/psum/psq
        launch_gemm(buf2d, wpg2 + (size_t)l * 2 * D_ * D_, pg_b2 + (size_t)l * D_,
                    pat, D_, 2 * D_, ACT_TANH_STABLE, sc + (size_t)l * D_, cur, psum, psq);
        // 4) es pre-LN = pat @ es_w + es_b
        launch_gemm(pat, wes + (size_t)l * D_ * D_, es_b + (size_t)l * D_,
                    tmp, D_, D_, ACT_NONE, nullptr, nullptr, nullptr, nullptr);
        // 5) emo += sigmoid(LN(.))
        ln_act_kernel<<<B_, 256>>>(tmp, es_g + (size_t)l * D_,
                                   es_be + (size_t)l * D_, nullptr, emo, D_, 1);
        // 6) q pre-LN = pat @ qg_w1 + b1   [B,H]
        launch_gemm(pat, wqg1 + (size_t)l * D_ * H_, qg_b1 + (size_t)l * H_,
                    tmp, H_, D_, ACT_NONE, nullptr, nullptr, nullptr, nullptr);
        // 7) ReLU(LN(.))
        ln_act_kernel<<<B_, 256>>>(tmp, qg_g1 + (size_t)l * H_,
                                   qg_be1 + (size_t)l * H_, tmp, nullptr, H_, 2);
        // 8) anchors[l] = . @ qg_w2 + b2 -> d_out
        launch_gemm(tmp, wqg2 + (size_t)l * H_ * D_, qg_b2 + (size_t)l * D_,
                    out_qa + (size_t)l * BD, D_, H_, ACT_NONE, nullptr, nullptr, nullptr, nullptr);
    }

    // outputs
    finalize_kernel<<<4096, 256>>>(psum, emo, out, tmp);
    launch_gemm(tmp, cmat, nullptr, out_cf, D_, D_, ACT_SIGMOID,
                nullptr, nullptr, nullptr, nullptr);
    stab_part_kernel<<<1024, 256>>>(psum, psq, part);
    stab_final_kernel<<<1, 256>>>(part, out_ss);
    (void)n_in; (void)out_size;
}

// round 4
// speedup vs baseline: 2.9474x; 1.0234x over previous
#include <cuda_runtime.h>
#include <math.h>
#include <stdint.h>

#define B_ 8192
#define D_ 1024
#define L_ 5
#define H_ 512
#define BD_ (B_ * D_)

// ================= scratch (device globals; no allocations) =================
__device__ float g_cur[B_ * D_];
__device__ float g_buf2d[B_ * 2 * D_];
__device__ float g_pat[B_ * D_];
__device__ float g_tmp[B_ * D_];
__device__ float g_emo[B_ * D_];
__device__ float g_psum[B_ * D_];
__device__ float g_psq[B_ * D_];
__device__ float g_cmat[D_ * D_];            // C[k][n] = 0.9^((n-k)%D), tf32-rounded
__device__ double g_part[1024];
// tf32-rounded weights (same [K,N] layout as inputs)
__device__ float g_wpg1[L_ * D_ * 2 * D_];
__device__ float g_wpg2[L_ * 2 * D_ * D_];
__device__ float g_wes [L_ * D_ * D_];
__device__ float g_wqg1[L_ * D_ * H_];
__device__ float g_wqg2[L_ * H_ * D_];

enum { ACT_NONE = 0, ACT_TANH_STABLE = 1, ACT_SIGMOID = 2 };

// ================= helpers =================
__device__ __forceinline__ float rna_tf32(float x) {
    float r;
    asm("cvt.rna.tf32.f32 %0, %1;" : "=f"(r) : "f"(x));
    return r;
}
__device__ __forceinline__ uint32_t smem_u32(const void* p) {
    uint32_t a;
    asm("{ .reg .u64 t; cvta.to.shared.u64 t, %1; cvt.u32.u64 %0, t; }"
        : "=r"(a) : "l"(p));
    return a;
}
__device__ __forceinline__ void cp16(uint32_t dst, const void* src) {
    asm volatile("cp.async.cg.shared.global [%0], [%1], 16;" :: "r"(dst), "l"(src));
}
__device__ __forceinline__ void cp_commit() {
    asm volatile("cp.async.commit_group;" ::: "memory");
}
template <int N>
__device__ __forceinline__ void cp_wait() {
    asm volatile("cp.async.wait_group %0;" :: "n"(N) : "memory");
}
__device__ __forceinline__ void mma_tf32(float* d, const uint32_t* a, const uint32_t* b) {
    asm volatile(
        "mma.sync.aligned.m16n8k8.row.col.f32.tf32.tf32.f32 "
        "{%0,%1,%2,%3}, {%4,%5,%6,%7}, {%8,%9}, {%0,%1,%2,%3};"
        : "+f"(d[0]), "+f"(d[1]), "+f"(d[2]), "+f"(d[3])
        : "r"(a[0]), "r"(a[1]), "r"(a[2]), "r"(a[3]), "r"(b[0]), "r"(b[1]));
}

// ================= tf32 tensor-core GEMM =================
// C[M,N] = act(A[M,K] @ W[K,N] + bias). A tf32-rounded [M,K] row-major,
// W tf32-rounded [K,N] row-major (acts as col-major B for mma row.col).
#define MT 128
#define NT 128
#define KC 32
#define STAGES 2
#define A_STRIDE 36                        // floats per A smem row (pad, conflict-free)
#define B_STRIDE 136                       // floats per B smem row (pad, conflict-free)
#define A_FLOATS (MT * A_STRIDE)           // 4608
#define B_FLOATS (KC * B_STRIDE)           // 4352
#define STAGE_FLOATS (A_FLOATS + B_FLOATS) // 8960
#define GEMM_SMEM (STAGES * STAGE_FLOATS * 4)  // 71680 bytes -> 2 CTAs/SM

__device__ __forceinline__ void copy_tiles(
    const float* __restrict__ A, const float* __restrict__ W, int N, int K,
    int rowBase, int colBase, int k0, uint32_t stageAddr, int tid)
{
    // A tile: 128 rows x 32 floats (8 x 16B per row) => 1024 cp16, 4/thread
#pragma unroll
    for (int j = 0; j < 4; j++) {
        int idx = tid + j * 256;
        int r = idx >> 3, c = idx & 7;
        const float* src = A + (size_t)(rowBase + r) * K + k0 + c * 4;
        cp16(stageAddr + (uint32_t)(r * A_STRIDE * 4 + c * 16), src);
    }
    // B tile: 32 k-rows x 128 floats (32 x 16B per row) => 1024 cp16, 4/thread
    const uint32_t bAddr = stageAddr + A_FLOATS * 4;
#pragma unroll
    for (int j = 0; j < 4; j++) {
        int idx = tid + j * 256;
        int kr = idx >> 5, c = idx & 31;
        const float* src = W + (size_t)(k0 + kr) * N + colBase + c * 4;
        cp16(bAddr + (uint32_t)(kr * B_STRIDE * 4 + c * 16), src);
    }
}

__global__ void __launch_bounds__(256, 2) mma_gemm(
    const float* __restrict__ A, const float* __restrict__ W,
    const float* __restrict__ bias, float* __restrict__ C,
    int N, int K, int act,
    const float* __restrict__ sc, float* __restrict__ curout,
    float* __restrict__ psum, float* __restrict__ psq)
{
    extern __shared__ float sm[];
    const uint32_t sb = smem_u32(sm);
    const int tid = threadIdx.x;
    const int wid = tid >> 5, lane = tid & 31;
    const int g = lane >> 2, tig = lane & 3;       // mma group / thread-in-group
    const int warp_m = wid & 1;                    // 0..1  (64 rows each)
    const int warp_n = wid >> 1;                   // 0..3  (32 cols each)
    const int rowBase = blockIdx.y * MT;
    const int colBase = blockIdx.x * NT;
    const int nk = K / KC;

    float acc[4][4][4];
#pragma unroll
    for (int mi = 0; mi < 4; mi++)
#pragma unroll
        for (int ni = 0; ni < 4; ni++)
#pragma unroll
            for (int q = 0; q < 4; q++) acc[mi][ni][q] = 0.f;

    // prologue: chunk 0 -> slot 0
    copy_tiles(A, W, N, K, rowBase, colBase, 0, sb, tid);
    cp_commit();

    for (int i = 0; i < nk; i++) {
        // prefetch chunk i+1 into slot (i+1)&1 (slot safe: chunk i-1 compute
        // finished at end-of-iteration sync of i-1), THEN wait for chunk i.
        if (i + 1 < nk) {
            copy_tiles(A, W, N, K, rowBase, colBase, (i + 1) * KC,
                       sb + (uint32_t)(((i + 1) & 1) * STAGE_FLOATS * 4), tid);
            cp_commit();
            cp_wait<1>();
        } else {
            cp_wait<0>();
        }
        __syncthreads();

        const float* As = sm + (i & 1) * STAGE_FLOATS;
        const float* Bs = As + A_FLOATS;
        const int arow0 = warp_m * 64;
        const int bcol0 = warp_n * 32;

#pragma unroll
        for (int ks = 0; ks < 4; ks++) {
            const int k0 = ks * 8;
            uint32_t af[4][4], bf[4][2];
#pragma unroll
            for (int mi = 0; mi < 4; mi++) {
                const float* ap = As + (arow0 + mi * 16 + g) * A_STRIDE + k0 + tig;
                af[mi][0] = __float_as_uint(ap[0]);
                af[mi][1] = __float_as_uint(ap[8 * A_STRIDE]);
                af[mi][2] = __float_as_uint(ap[4]);
                af[mi][3] = __float_as_uint(ap[8 * A_STRIDE + 4]);
            }
#pragma unroll
            for (int ni = 0; ni < 4; ni++) {
                const float* bp = Bs + (k0 + tig) * B_STRIDE + bcol0 + ni * 8 + g;
                bf[ni][0] = __float_as_uint(bp[0]);
                bf[ni][1] = __float_as_uint(bp[4 * B_STRIDE]);
            }
#pragma unroll
            for (int mi = 0; mi < 4; mi++)
#pragma unroll
                for (int ni = 0; ni < 4; ni++)
                    mma_tf32(acc[mi][ni], af[mi], bf[ni]);
        }
        __syncthreads();
    }

    // ---------------- fused epilogue ----------------
#pragma unroll
    for (int mi = 0; mi < 4; mi++) {
        const int r0 = rowBase + warp_m * 64 + mi * 16 + g;
#pragma unroll
        for (int ni = 0; ni < 4; ni++) {
            const int c0 = colBase + warp_n * 32 + ni * 8 + tig * 2;
#pragma unroll
            for (int q = 0; q < 4; q++) {
                const int row = r0 + (q >> 1) * 8;
                const int col = c0 + (q & 1);
                float v = acc[mi][ni][q];
                size_t idx = (size_t)row * N + col;
                if (act == ACT_NONE) {
                    C[idx] = v + bias[col];
                } else if (act == ACT_SIGMOID) {
                    C[idx] = 1.f / (1.f + expf(-v));
                } else {  // ACT_TANH_STABLE
                    v += bias[col];
                    float p = tanhf(v);
                    float s = p * (1.f / (1.f + expf(-sc[col])));
                    C[idx] = rna_tf32(p);        // pat: GEMM input -> rounded
                    curout[idx] = rna_tf32(s);   // next-layer GEMM input -> rounded
                    psum[idx] += s;              // output path: full fp32
                    psq[idx] += s * s;
                }
            }
        }
    }
}

// ================= LayerNorm + activation =================
// act: 0 = GELU(exact)->out (tf32-rounded), 1 = sigmoid->accum+=, 2 = ReLU->out (rounded)
__global__ void __launch_bounds__(256) ln_act_kernel(
    const float* __restrict__ in, const float* __restrict__ g,
    const float* __restrict__ be, float* __restrict__ out,
    float* __restrict__ accum, int N, int act)
{
    const int row = blockIdx.x;
    const float* x = in + (size_t)row * N;
    const int per = N >> 8;
    float vals[8];
    float s = 0.f, ss = 0.f;
    for (int t = 0; t < per; t++) {
        float v = x[threadIdx.x + (t << 8)];
        vals[t] = v;
        s += v;
        ss += v * v;
    }
#pragma unroll
    for (int o = 16; o > 0; o >>= 1) {
        s += __shfl_down_sync(0xffffffff, s, o);
        ss += __shfl_down_sync(0xffffffff, ss, o);
    }
    __shared__ float sm[16];
    __shared__ float s_mean, s_rstd;
    const int w = threadIdx.x >> 5, lane = threadIdx.x & 31;
    if (lane == 0) { sm[w] = s; sm[8 + w] = ss; }
    __syncthreads();
    if (threadIdx.x == 0) {
        float S = 0.f, SS = 0.f;
        for (int i = 0; i < 8; i++) { S += sm[i]; SS += sm[8 + i]; }
        float m = S / (float)N;
        float var = SS / (float)N - m * m;
        s_mean = m;
        s_rstd = rsqrtf(var + 1e-5f);
    }
    __syncthreads();
    const float m = s_mean, r = s_rstd;
    for (int t = 0; t < per; t++) {
        int c = threadIdx.x + (t << 8);
        float v = (vals[t] - m) * r * g[c] + be[c];
        size_t idx = (size_t)row * N + c;
        if (act == 0) {
            out[idx] = rna_tf32(0.5f * v * (1.f + erff(v * 0.70710678118654752f)));
        } else if (act == 1) {
            accum[idx] += 1.f / (1.f + expf(-v));
        } else {
            out[idx] = rna_tf32(fmaxf(v, 0.f));
        }
    }
}

// ================= small kernels =================
__global__ void __launch_bounds__(256) zero3_kernel(float* a, float* b, float* c, int n) {
    for (int i = blockIdx.x * 256 + threadIdx.x; i < n; i += gridDim.x * 256) {
        a[i] = 0.f; b[i] = 0.f; c[i] = 0.f;
    }
}

__global__ void __launch_bounds__(256) rna_copy_kernel(const float* __restrict__ in,
                                                       float* __restrict__ out, int n) {
    for (int i = blockIdx.x * 256 + threadIdx.x; i < n; i += gridDim.x * 256)
        out[i] = rna_tf32(in[i]);
}

// fused weight rounding: 5 segments in one launch (keeps launch count low so
// mma_gemm is the 5th launch -> ncu profiles it)
__global__ void __launch_bounds__(256) wround_kernel(
    const float* s1, float* d1, int n1, const float* s2, float* d2, int n2,
    const float* s3, float* d3, int n3, const float* s4, float* d4, int n4,
    const float* s5, float* d5, int n5)
{
    const int stride = gridDim.x * 256;
    const int t0 = blockIdx.x * 256 + threadIdx.x;
    for (int i = t0; i < n1; i += stride) d1[i] = rna_tf32(s1[i]);
    for (int i = t0; i < n2; i += stride) d2[i] = rna_tf32(s2[i]);
    for (int i = t0; i < n3; i += stride) d3[i] = rna_tf32(s3[i]);
    for (int i = t0; i < n4; i += stride) d4[i] = rna_tf32(s4[i]);
    for (int i = t0; i < n5; i += stride) d5[i] = rna_tf32(s5[i]);
}

// C[k][n] = 0.9^((n-k) mod D), tf32-rounded
__global__ void __launch_bounds__(256) cinit_kernel(float* C) {
    int idx = blockIdx.x * 256 + threadIdx.x;
    int k = idx >> 10;
    int n = idx & (D_ - 1);
    int e = (n - k + D_) & (D_ - 1);
    C[idx] = rna_tf32(powf(0.9f, (float)e));
}

__global__ void __launch_bounds__(256) finalize_kernel(
    const float* __restrict__ ps, const float* __restrict__ es,
    float* __restrict__ out, float* __restrict__ rcp) {
    for (int i = blockIdx.x * 256 + threadIdx.x; i < BD_; i += gridDim.x * 256) {
        float cp = ps[i] * 0.2f;
        out[i] = cp;
        out[(size_t)BD_ + i] = es[i] * 0.2f;
        rcp[i] = rna_tf32(cp);
    }
}

__global__ void __launch_bounds__(256) stab_part_kernel(
    const float* __restrict__ ps, const float* __restrict__ psq, double* __restrict__ part) {
    double acc = 0.0;
    for (int i = blockIdx.x * 256 + threadIdx.x; i < BD_; i += gridDim.x * 256) {
        float s = ps[i], q = psq[i];
        acc += (double)((q - s * s * 0.2f) * 0.25f);
    }
#pragma unroll
    for (int o = 16; o > 0; o >>= 1)
        acc += __shfl_down_sync(0xffffffff, acc, o);
    __shared__ double sm[8];
    int w = threadIdx.x >> 5, lane = threadIdx.x & 31;
    if (lane == 0) sm[w] = acc;
    __syncthreads();
    if (threadIdx.x == 0) {
        double t = 0.0;
        for (int i = 0; i < 8; i++) t += sm[i];
        part[blockIdx.x] = t;
    }
}

__global__ void __launch_bounds__(256) stab_final_kernel(const double* __restrict__ part,
                                                         float* __restrict__ out) {
    double acc = 0.0;
    for (int i = threadIdx.x; i < 1024; i += 256) acc += part[i];
#pragma unroll
    for (int o = 16; o > 0; o >>= 1)
        acc += __shfl_down_sync(0xffffffff, acc, o);
    __shared__ double sm[8];
    int w = threadIdx.x >> 5, lane = threadIdx.x & 31;
    if (lane == 0) sm[w] = acc;
    __syncthreads();
    if (threadIdx.x == 0) {
        double t = 0.0;
        for (int i = 0; i < 8; i++) t += sm[i];
        out[0] = (float)(1.0 - t / (double)BD_);
    }
}

// ================= host launch =================
static inline void launch_gemm(const float* A, const float* W, const float* bias,
                               float* C, int N, int K, int act,
                               const float* sc, float* curout, float* psum, float* psq) {
    dim3 grid(N / NT, B_ / MT);
    mma_gemm<<<grid, 256, GEMM_SMEM>>>(A, W, bias, C, N, K, act, sc, curout, psum, psq);
}

extern "C" void kernel_launch(void* const* d_in, const int* in_sizes, int n_in,
                              void* d_out, int out_size)
{
    const float* seed = (const float*)d_in[0];
    const int o = (in_sizes[1] == 1) ? 2 : 1;
    const float* pg_w1 = (const float*)d_in[o + 0];
    const float* pg_b1 = (const float*)d_in[o + 1];
    const float* pg_g1 = (const float*)d_in[o + 2];
    const float* pg_be1 = (const float*)d_in[o + 3];
    const float* pg_w2 = (const float*)d_in[o + 4];
    const float* pg_b2 = (const float*)d_in[o + 5];
    const float* es_w = (const float*)d_in[o + 6];
    const float* es_b = (const float*)d_in[o + 7];
    const float* es_g = (const float*)d_in[o + 8];
    const float* es_be = (const float*)d_in[o + 9];
    const float* qg_w1 = (const float*)d_in[o + 10];
    const float* qg_b1 = (const float*)d_in[o + 11];
    const float* qg_g1 = (const float*)d_in[o + 12];
    const float* qg_be1 = (const float*)d_in[o + 13];
    const float* qg_w2 = (const float*)d_in[o + 14];
    const float* qg_b2 = (const float*)d_in[o + 15];
    const float* sc = (const float*)d_in[o + 16];
    float* out = (float*)d_out;

    float *cur, *buf2d, *pat, *tmp, *emo, *psum, *psq, *cmat;
    float *wpg1, *wpg2, *wes, *wqg1, *wqg2;
    double* part;
    cudaGetSymbolAddress((void**)&cur, g_cur);
    cudaGetSymbolAddress((void**)&buf2d, g_buf2d);
    cudaGetSymbolAddress((void**)&pat, g_pat);
    cudaGetSymbolAddress((void**)&tmp, g_tmp);
    cudaGetSymbolAddress((void**)&emo, g_emo);
    cudaGetSymbolAddress((void**)&psum, g_psum);
    cudaGetSymbolAddress((void**)&psq, g_psq);
    cudaGetSymbolAddress((void**)&cmat, g_cmat);
    cudaGetSymbolAddress((void**)&part, g_part);
    cudaGetSymbolAddress((void**)&wpg1, g_wpg1);
    cudaGetSymbolAddress((void**)&wpg2, g_wpg2);
    cudaGetSymbolAddress((void**)&wes, g_wes);
    cudaGetSymbolAddress((void**)&wqg1, g_wqg1);
    cudaGetSymbolAddress((void**)&wqg2, g_wqg2);

    cudaFuncSetAttribute(mma_gemm, cudaFuncAttributeMaxDynamicSharedMemorySize, GEMM_SMEM);

    const size_t BD = (size_t)BD_;
    float* out_cf = out + 2 * BD;
    float* out_ss = out + 3 * BD;
    float* out_qa = out + 3 * BD + 1;

    // launches 1..4 (then GEMM1 is launch #5, the one ncu profiles)
    zero3_kernel<<<4096, 256>>>(psum, psq, emo, BD_);
    rna_copy_kernel<<<4096, 256>>>(seed, cur, BD_);
    cinit_kernel<<<(D_ * D_) / 256, 256>>>(cmat);
    wround_kernel<<<8192, 256>>>(pg_w1, wpg1, L_ * D_ * 2 * D_,
                                 pg_w2, wpg2, L_ * 2 * D_ * D_,
                                 es_w, wes, L_ * D_ * D_,
                                 qg_w1, wqg1, L_ * D_ * H_,
                                 qg_w2, wqg2, L_ * H_ * D_);

    for (int l = 0; l < L_; l++) {
        // 1) pre1 = cur @ pg_w1 + b1   [B,2D]
        launch_gemm(cur, wpg1 + (size_t)l * D_ * 2 * D_, pg_b1 + (size_t)l * 2 * D_,
                    buf2d, 2 * D_, D_, ACT_NONE, nullptr, nullptr, nullptr, nullptr);
        // 2) h = GELU(LN(pre1))
        ln_act_kernel<<<B_, 256>>>(buf2d, pg_g1 + (size_t)l * 2 * D_,
                                   pg_be1 + (size_t)l * 2 * D_, buf2d, nullptr, 2 * D_, 0);
        // 3) pat = tanh(h @ pg_w2 + b2); fused stable/cur/psum/psq
        launch_gemm(buf2d, wpg2 + (size_t)l * 2 * D_ * D_, pg_b2 + (size_t)l * D_,
                    pat, D_, 2 * D_, ACT_TANH_STABLE, sc + (size_t)l * D_, cur, psum, psq);
        // 4) es pre-LN = pat @ es_w + es_b
        launch_gemm(pat, wes + (size_t)l * D_ * D_, es_b + (size_t)l * D_,
                    tmp, D_, D_, ACT_NONE, nullptr, nullptr, nullptr, nullptr);
        // 5) emo += sigmoid(LN(.))
        ln_act_kernel<<<B_, 256>>>(tmp, es_g + (size_t)l * D_,
                                   es_be + (size_t)l * D_, nullptr, emo, D_, 1);
        // 6) q pre-LN = pat @ qg_w1 + b1   [B,H]
        launch_gemm(pat, wqg1 + (size_t)l * D_ * H_, qg_b1 + (size_t)l * H_,
                    tmp, H_, D_, ACT_NONE, nullptr, nullptr, nullptr, nullptr);
        // 7) ReLU(LN(.))
        ln_act_kernel<<<B_, 256>>>(tmp, qg_g1 + (size_t)l * H_,
                                   qg_be1 + (size_t)l * H_, tmp, nullptr, H_, 2);
        // 8) anchors[l] = . @ qg_w2 + b2 -> d_out
        launch_gemm(tmp, wqg2 + (size_t)l * H_ * D_, qg_b2 + (size_t)l * D_,
                    out_qa + (size_t)l * BD, D_, H_, ACT_NONE, nullptr, nullptr, nullptr, nullptr);
    }

    // outputs
    finalize_kernel<<<4096, 256>>>(psum, emo, out, tmp);
    launch_gemm(tmp, cmat, nullptr, out_cf, D_, D_, ACT_SIGMOID,
                nullptr, nullptr, nullptr, nullptr);
    stab_part_kernel<<<1024, 256>>>(psum, psq, part);
    stab_final_kernel<<<1, 256>>>(part, out_ss);
    (void)n_in; (void)out_size;
}

// round 5
// speedup vs baseline: 5.2810x; 1.7917x over previous
#include <cuda_runtime.h>
#include <cuda_fp16.h>
#include <math.h>
#include <stdint.h>

#define B_ 8192
#define D_ 1024
#define L_ 5
#define H_ 512
#define BD_ (B_ * D_)

// ================= scratch (device globals; no allocations) =================
__device__ __half g_cur[B_ * D_];
__device__ float  g_buf2d[B_ * 2 * D_];       // pre-LN float
__device__ __half g_buf2dh[B_ * 2 * D_];      // GELU(LN(.)) half (GEMM input)
__device__ __half g_pat[B_ * D_];
__device__ float  g_tmp[B_ * D_];             // pre-LN float (es / qg1)
__device__ __half g_tmph[B_ * D_];            // ReLU(LN(.)) half
__device__ float  g_emo[B_ * D_];
__device__ float  g_psum[B_ * D_];
__device__ float  g_psq[B_ * D_];
__device__ __half g_cmat[D_ * D_];            // C[k][n] = 0.9^((n-k)%D), half
__device__ __half g_rcp[B_ * D_];             // combined pattern, half
__device__ double g_part[1024];
// half weights (same [K,N] layout as inputs)
__device__ __half g_wpg1[L_ * D_ * 2 * D_];
__device__ __half g_wpg2[L_ * 2 * D_ * D_];
__device__ __half g_wes [L_ * D_ * D_];
__device__ __half g_wqg1[L_ * D_ * H_];
__device__ __half g_wqg2[L_ * H_ * D_];

enum { ACT_NONE = 0, ACT_TANH_STABLE = 1, ACT_SIGMOID = 2 };

// ================= helpers =================
__device__ __forceinline__ uint32_t smem_u32(const void* p) {
    uint32_t a;
    asm("{ .reg .u64 t; cvta.to.shared.u64 t, %1; cvt.u32.u64 %0, t; }"
        : "=r"(a) : "l"(p));
    return a;
}
__device__ __forceinline__ void cp16(uint32_t dst, const void* src) {
    asm volatile("cp.async.cg.shared.global [%0], [%1], 16;" :: "r"(dst), "l"(src));
}
__device__ __forceinline__ void cp_commit() {
    asm volatile("cp.async.commit_group;" ::: "memory");
}
template <int N>
__device__ __forceinline__ void cp_wait() {
    asm volatile("cp.async.wait_group %0;" :: "n"(N) : "memory");
}
__device__ __forceinline__ void ldm_x4(uint32_t* r, uint32_t addr) {
    asm volatile("ldmatrix.sync.aligned.m8n8.x4.shared.b16 {%0,%1,%2,%3}, [%4];"
                 : "=r"(r[0]), "=r"(r[1]), "=r"(r[2]), "=r"(r[3]) : "r"(addr));
}
__device__ __forceinline__ void ldm_x4_trans(uint32_t* r, uint32_t addr) {
    asm volatile("ldmatrix.sync.aligned.m8n8.x4.trans.shared.b16 {%0,%1,%2,%3}, [%4];"
                 : "=r"(r[0]), "=r"(r[1]), "=r"(r[2]), "=r"(r[3]) : "r"(addr));
}
__device__ __forceinline__ void mma_f16(float* d, const uint32_t* a, const uint32_t* b) {
    asm volatile(
        "mma.sync.aligned.m16n8k16.row.col.f32.f16.f16.f32 "
        "{%0,%1,%2,%3}, {%4,%5,%6,%7}, {%8,%9}, {%0,%1,%2,%3};"
        : "+f"(d[0]), "+f"(d[1]), "+f"(d[2]), "+f"(d[3])
        : "r"(a[0]), "r"(a[1]), "r"(a[2]), "r"(a[3]), "r"(b[0]), "r"(b[1]));
}

// ================= fp16 tensor-core GEMM =================
// C[M,N] = act(A[M,K] @ W[K,N] + bias). A half [M,K] row-major,
// W half [K,N] row-major (B operand via ldmatrix.trans).
#define MT 128
#define NT 128
#define KC 64
#define A_BYTES (MT * KC * 2)              // 16384  (row = 128B)
#define B_BYTES (KC * NT * 2)              // 16384  (row = 256B)
#define STAGE_BYTES (A_BYTES + B_BYTES)    // 32768
#define GEMM_SMEM (2 * STAGE_BYTES)        // 65536 -> 2 CTAs/SM

__device__ __forceinline__ void copy_tiles(
    const __half* __restrict__ A, const __half* __restrict__ W, int N, int K,
    int rowBase, int colBase, int k0, uint32_t stageAddr, int tid)
{
    // A tile: 128 rows x 64 halves (8 x 16B per row) => 1024 cp16, 4/thread
#pragma unroll
    for (int j = 0; j < 4; j++) {
        int idx = tid + j * 256;
        int r = idx >> 3, c = idx & 7;
        const __half* src = A + (size_t)(rowBase + r) * K + k0 + c * 8;
        uint32_t off = (uint32_t)(r * 128 + c * 16);
        cp16(stageAddr + (off ^ ((off >> 3) & 0x70)), src);
    }
    // B tile: 64 k-rows x 128 halves (16 x 16B per row) => 1024 cp16, 4/thread
    const uint32_t bAddr = stageAddr + A_BYTES;
#pragma unroll
    for (int j = 0; j < 4; j++) {
        int idx = tid + j * 256;
        int kr = idx >> 4, c = idx & 15;
        const __half* src = W + (size_t)(k0 + kr) * N + colBase + c * 8;
        uint32_t off = (uint32_t)(kr * 256 + c * 16);
        cp16(bAddr + (off ^ ((off >> 4) & 0x70)), src);
    }
}

__global__ void __launch_bounds__(256, 2) mma_gemm(
    const __half* __restrict__ A, const __half* __restrict__ W,
    const float* __restrict__ bias, float* __restrict__ Cf, __half* __restrict__ Ch,
    int N, int K, int act,
    const float* __restrict__ sc, __half* __restrict__ curout,
    float* __restrict__ psum, float* __restrict__ psq)
{
    extern __shared__ char smemraw[];
    const uint32_t sb = smem_u32(smemraw);
    const int tid = threadIdx.x;
    const int wid = tid >> 5, lane = tid & 31;
    const int g = lane >> 2, tig = lane & 3;
    const int warp_m = wid & 1;                    // 0..1 (64 rows)
    const int warp_n = wid >> 1;                   // 0..3 (32 cols)
    const int rowBase = blockIdx.y * MT;
    const int colBase = blockIdx.x * NT;
    const int nk = K / KC;

    // ldmatrix lane addressing
    const int lr = (lane & 7) + ((lane >> 3) & 1) * 8;   // row 0..15 within 16-blk
    const int lc16 = ((lane >> 4) & 1) * 16;             // 16B column selector

    float acc[4][4][4];
#pragma unroll
    for (int mi = 0; mi < 4; mi++)
#pragma unroll
        for (int ni = 0; ni < 4; ni++)
#pragma unroll
            for (int q = 0; q < 4; q++) acc[mi][ni][q] = 0.f;

    copy_tiles(A, W, N, K, rowBase, colBase, 0, sb, tid);
    cp_commit();

    const int arow0 = warp_m * 64;
    const int bcol0 = warp_n * 32;

    for (int i = 0; i < nk; i++) {
        if (i + 1 < nk) {
            copy_tiles(A, W, N, K, rowBase, colBase, (i + 1) * KC,
                       sb + (uint32_t)(((i + 1) & 1) * STAGE_BYTES), tid);
            cp_commit();
            cp_wait<1>();
        } else {
            cp_wait<0>();
        }
        __syncthreads();

        const uint32_t aBase = sb + (uint32_t)((i & 1) * STAGE_BYTES);
        const uint32_t bBase = aBase + A_BYTES;

#pragma unroll
        for (int ks = 0; ks < 4; ks++) {            // 4 x k16 per KC=64
            uint32_t af[4][4], bf[4][2];
#pragma unroll
            for (int mi = 0; mi < 4; mi++) {
                uint32_t off = (uint32_t)((arow0 + mi * 16 + lr) * 128 + ks * 32 + lc16);
                ldm_x4(af[mi], aBase + (off ^ ((off >> 3) & 0x70)));
            }
#pragma unroll
            for (int p = 0; p < 2; p++) {           // each covers 2 n8 tiles
                uint32_t off = (uint32_t)((ks * 16 + lr) * 256 +
                                          (bcol0 + p * 16) * 2 + lc16);
                uint32_t r[4];
                ldm_x4_trans(r, bBase + (off ^ ((off >> 4) & 0x70)));
                bf[2 * p][0] = r[0]; bf[2 * p][1] = r[1];
                bf[2 * p + 1][0] = r[2]; bf[2 * p + 1][1] = r[3];
            }
#pragma unroll
            for (int mi = 0; mi < 4; mi++)
#pragma unroll
                for (int ni = 0; ni < 4; ni++)
                    mma_f16(acc[mi][ni], af[mi], bf[ni]);
        }
        __syncthreads();
    }

    // ---------------- fused epilogue ----------------
#pragma unroll
    for (int mi = 0; mi < 4; mi++) {
        const int r0 = rowBase + warp_m * 64 + mi * 16 + g;
#pragma unroll
        for (int ni = 0; ni < 4; ni++) {
            const int c0 = colBase + warp_n * 32 + ni * 8 + tig * 2;
#pragma unroll
            for (int q = 0; q < 4; q++) {
                const int row = r0 + (q >> 1) * 8;
                const int col = c0 + (q & 1);
                float v = acc[mi][ni][q];
                size_t idx = (size_t)row * N + col;
                if (act == ACT_NONE) {
                    Cf[idx] = v + bias[col];
                } else if (act == ACT_SIGMOID) {
                    Cf[idx] = 1.f / (1.f + expf(-v));
                } else {  // ACT_TANH_STABLE
                    v += bias[col];
                    float p = tanhf(v);
                    float s = p * (1.f / (1.f + expf(-sc[col])));
                    Ch[idx] = __float2half_rn(p);
                    curout[idx] = __float2half_rn(s);
                    psum[idx] += s;
                    psq[idx] += s * s;
                }
            }
        }
    }
}

// ================= LayerNorm + activation =================
// act: 0 = GELU(exact)->half out, 1 = sigmoid->float accum+=, 2 = ReLU->half out
__global__ void __launch_bounds__(256) ln_act_kernel(
    const float* __restrict__ in, const float* __restrict__ g,
    const float* __restrict__ be, __half* __restrict__ outh,
    float* __restrict__ accum, int N, int act)
{
    const int row = blockIdx.x;
    const float* x = in + (size_t)row * N;
    const int per = N >> 8;
    float vals[8];
    float s = 0.f, ss = 0.f;
    for (int t = 0; t < per; t++) {
        float v = x[threadIdx.x + (t << 8)];
        vals[t] = v;
        s += v;
        ss += v * v;
    }
#pragma unroll
    for (int o = 16; o > 0; o >>= 1) {
        s += __shfl_down_sync(0xffffffff, s, o);
        ss += __shfl_down_sync(0xffffffff, ss, o);
    }
    __shared__ float sm[16];
    __shared__ float s_mean, s_rstd;
    const int w = threadIdx.x >> 5, lane = threadIdx.x & 31;
    if (lane == 0) { sm[w] = s; sm[8 + w] = ss; }
    __syncthreads();
    if (threadIdx.x == 0) {
        float S = 0.f, SS = 0.f;
        for (int i = 0; i < 8; i++) { S += sm[i]; SS += sm[8 + i]; }
        float m = S / (float)N;
        float var = SS / (float)N - m * m;
        s_mean = m;
        s_rstd = rsqrtf(var + 1e-5f);
    }
    __syncthreads();
    const float m = s_mean, r = s_rstd;
    for (int t = 0; t < per; t++) {
        int c = threadIdx.x + (t << 8);
        float v = (vals[t] - m) * r * g[c] + be[c];
        size_t idx = (size_t)row * N + c;
        if (act == 0) {
            outh[idx] = __float2half_rn(0.5f * v * (1.f + erff(v * 0.70710678118654752f)));
        } else if (act == 1) {
            accum[idx] += 1.f / (1.f + expf(-v));
        } else {
            outh[idx] = __float2half_rn(fmaxf(v, 0.f));
        }
    }
}

// ================= small kernels =================
__global__ void __launch_bounds__(256) zero3_kernel(float* a, float* b, float* c, int n) {
    for (int i = blockIdx.x * 256 + threadIdx.x; i < n; i += gridDim.x * 256) {
        a[i] = 0.f; b[i] = 0.f; c[i] = 0.f;
    }
}

__global__ void __launch_bounds__(256) h_copy_kernel(const float* __restrict__ in,
                                                     __half* __restrict__ out, int n) {
    for (int i = blockIdx.x * 256 + threadIdx.x; i < n; i += gridDim.x * 256)
        out[i] = __float2half_rn(in[i]);
}

// fused weight rounding: 5 segments, one launch
__global__ void __launch_bounds__(256) wround_kernel(
    const float* s1, __half* d1, int n1, const float* s2, __half* d2, int n2,
    const float* s3, __half* d3, int n3, const float* s4, __half* d4, int n4,
    const float* s5, __half* d5, int n5)
{
    const int stride = gridDim.x * 256;
    const int t0 = blockIdx.x * 256 + threadIdx.x;
    for (int i = t0; i < n1; i += stride) d1[i] = __float2half_rn(s1[i]);
    for (int i = t0; i < n2; i += stride) d2[i] = __float2half_rn(s2[i]);
    for (int i = t0; i < n3; i += stride) d3[i] = __float2half_rn(s3[i]);
    for (int i = t0; i < n4; i += stride) d4[i] = __float2half_rn(s4[i]);
    for (int i = t0; i < n5; i += stride) d5[i] = __float2half_rn(s5[i]);
}

// C[k][n] = 0.9^((n-k) mod D), half
__global__ void __launch_bounds__(256) cinit_kernel(__half* C) {
    int idx = blockIdx.x * 256 + threadIdx.x;
    int k = idx >> 10;
    int n = idx & (D_ - 1);
    int e = (n - k + D_) & (D_ - 1);
    C[idx] = __float2half_rn(powf(0.9f, (float)e));
}

__global__ void __launch_bounds__(256) finalize_kernel(
    const float* __restrict__ ps, const float* __restrict__ es,
    float* __restrict__ out, __half* __restrict__ rcp) {
    for (int i = blockIdx.x * 256 + threadIdx.x; i < BD_; i += gridDim.x * 256) {
        float cp = ps[i] * 0.2f;
        out[i] = cp;
        out[(size_t)BD_ + i] = es[i] * 0.2f;
        rcp[i] = __float2half_rn(cp);
    }
}

__global__ void __launch_bounds__(256) stab_part_kernel(
    const float* __restrict__ ps, const float* __restrict__ psq, double* __restrict__ part) {
    double acc = 0.0;
    for (int i = blockIdx.x * 256 + threadIdx.x; i < BD_; i += gridDim.x * 256) {
        float s = ps[i], q = psq[i];
        acc += (double)((q - s * s * 0.2f) * 0.25f);
    }
#pragma unroll
    for (int o = 16; o > 0; o >>= 1)
        acc += __shfl_down_sync(0xffffffff, acc, o);
    __shared__ double sm[8];
    int w = threadIdx.x >> 5, lane = threadIdx.x & 31;
    if (lane == 0) sm[w] = acc;
    __syncthreads();
    if (threadIdx.x == 0) {
        double t = 0.0;
        for (int i = 0; i < 8; i++) t += sm[i];
        part[blockIdx.x] = t;
    }
}

__global__ void __launch_bounds__(256) stab_final_kernel(const double* __restrict__ part,
                                                         float* __restrict__ out) {
    double acc = 0.0;
    for (int i = threadIdx.x; i < 1024; i += 256) acc += part[i];
#pragma unroll
    for (int o = 16; o > 0; o >>= 1)
        acc += __shfl_down_sync(0xffffffff, acc, o);
    __shared__ double sm[8];
    int w = threadIdx.x >> 5, lane = threadIdx.x & 31;
    if (lane == 0) sm[w] = acc;
    __syncthreads();
    if (threadIdx.x == 0) {
        double t = 0.0;
        for (int i = 0; i < 8; i++) t += sm[i];
        out[0] = (float)(1.0 - t / (double)BD_);
    }
}

// ================= host launch =================
static inline void launch_gemm(const __half* A, const __half* W, const float* bias,
                               float* Cf, __half* Ch, int N, int K, int act,
                               const float* sc, __half* curout, float* psum, float* psq) {
    dim3 grid(N / NT, B_ / MT);
    mma_gemm<<<grid, 256, GEMM_SMEM>>>(A, W, bias, Cf, Ch, N, K, act, sc, curout, psum, psq);
}

extern "C" void kernel_launch(void* const* d_in, const int* in_sizes, int n_in,
                              void* d_out, int out_size)
{
    const float* seed = (const float*)d_in[0];
    const int o = (in_sizes[1] == 1) ? 2 : 1;
    const float* pg_w1 = (const float*)d_in[o + 0];
    const float* pg_b1 = (const float*)d_in[o + 1];
    const float* pg_g1 = (const float*)d_in[o + 2];
    const float* pg_be1 = (const float*)d_in[o + 3];
    const float* pg_w2 = (const float*)d_in[o + 4];
    const float* pg_b2 = (const float*)d_in[o + 5];
    const float* es_w = (const float*)d_in[o + 6];
    const float* es_b = (const float*)d_in[o + 7];
    const float* es_g = (const float*)d_in[o + 8];
    const float* es_be = (const float*)d_in[o + 9];
    const float* qg_w1 = (const float*)d_in[o + 10];
    const float* qg_b1 = (const float*)d_in[o + 11];
    const float* qg_g1 = (const float*)d_in[o + 12];
    const float* qg_be1 = (const float*)d_in[o + 13];
    const float* qg_w2 = (const float*)d_in[o + 14];
    const float* qg_b2 = (const float*)d_in[o + 15];
    const float* sc = (const float*)d_in[o + 16];
    float* out = (float*)d_out;

    __half *cur, *buf2dh, *pat, *tmph, *cmat, *rcp;
    __half *wpg1, *wpg2, *wes, *wqg1, *wqg2;
    float *buf2d, *tmp, *emo, *psum, *psq;
    double* part;
    cudaGetSymbolAddress((void**)&cur, g_cur);
    cudaGetSymbolAddress((void**)&buf2d, g_buf2d);
    cudaGetSymbolAddress((void**)&buf2dh, g_buf2dh);
    cudaGetSymbolAddress((void**)&pat, g_pat);
    cudaGetSymbolAddress((void**)&tmp, g_tmp);
    cudaGetSymbolAddress((void**)&tmph, g_tmph);
    cudaGetSymbolAddress((void**)&emo, g_emo);
    cudaGetSymbolAddress((void**)&psum, g_psum);
    cudaGetSymbolAddress((void**)&psq, g_psq);
    cudaGetSymbolAddress((void**)&cmat, g_cmat);
    cudaGetSymbolAddress((void**)&rcp, g_rcp);
    cudaGetSymbolAddress((void**)&part, g_part);
    cudaGetSymbolAddress((void**)&wpg1, g_wpg1);
    cudaGetSymbolAddress((void**)&wpg2, g_wpg2);
    cudaGetSymbolAddress((void**)&wes, g_wes);
    cudaGetSymbolAddress((void**)&wqg1, g_wqg1);
    cudaGetSymbolAddress((void**)&wqg2, g_wqg2);

    cudaFuncSetAttribute(mma_gemm, cudaFuncAttributeMaxDynamicSharedMemorySize, GEMM_SMEM);

    const size_t BD = (size_t)BD_;
    float* out_cf = out + 2 * BD;
    float* out_ss = out + 3 * BD;
    float* out_qa = out + 3 * BD + 1;

    // launches 1..4, then GEMM1 is launch #5 (ncu profiles it)
    zero3_kernel<<<4096, 256>>>(psum, psq, emo, BD_);
    h_copy_kernel<<<4096, 256>>>(seed, cur, BD_);
    cinit_kernel<<<(D_ * D_) / 256, 256>>>(cmat);
    wround_kernel<<<8192, 256>>>(pg_w1, wpg1, L_ * D_ * 2 * D_,
                                 pg_w2, wpg2, L_ * 2 * D_ * D_,
                                 es_w, wes, L_ * D_ * D_,
                                 qg_w1, wqg1, L_ * D_ * H_,
                                 qg_w2, wqg2, L_ * H_ * D_);

    for (int l = 0; l < L_; l++) {
        // 1) pre1 = cur @ pg_w1 + b1   [B,2D] float
        launch_gemm(cur, wpg1 + (size_t)l * D_ * 2 * D_, pg_b1 + (size_t)l * 2 * D_,
                    buf2d, nullptr, 2 * D_, D_, ACT_NONE, nullptr, nullptr, nullptr, nullptr);
        // 2) h = GELU(LN(pre1)) -> half
        ln_act_kernel<<<B_, 256>>>(buf2d, pg_g1 + (size_t)l * 2 * D_,
                                   pg_be1 + (size_t)l * 2 * D_, buf2dh, nullptr, 2 * D_, 0);
        // 3) pat = tanh(h @ pg_w2 + b2); fused stable/cur/psum/psq
        launch_gemm(buf2dh, wpg2 + (size_t)l * 2 * D_ * D_, pg_b2 + (size_t)l * D_,
                    nullptr, pat, D_, 2 * D_, ACT_TANH_STABLE, sc + (size_t)l * D_,
                    cur, psum, psq);
        // 4) es pre-LN = pat @ es_w + es_b  -> float
        launch_gemm(pat, wes + (size_t)l * D_ * D_, es_b + (size_t)l * D_,
                    tmp, nullptr, D_, D_, ACT_NONE, nullptr, nullptr, nullptr, nullptr);
        // 5) emo += sigmoid(LN(.))
        ln_act_kernel<<<B_, 256>>>(tmp, es_g + (size_t)l * D_,
                                   es_be + (size_t)l * D_, nullptr, emo, D_, 1);
        // 6) q pre-LN = pat @ qg_w1 + b1   [B,H] float
        launch_gemm(pat, wqg1 + (size_t)l * D_ * H_, qg_b1 + (size_t)l * H_,
                    tmp, nullptr, H_, D_, ACT_NONE, nullptr, nullptr, nullptr, nullptr);
        // 7) ReLU(LN(.)) -> half
        ln_act_kernel<<<B_, 256>>>(tmp, qg_g1 + (size_t)l * H_,
                                   qg_be1 + (size_t)l * H_, tmph, nullptr, H_, 2);
        // 8) anchors[l] = . @ qg_w2 + b2 -> d_out (float)
        launch_gemm(tmph, wqg2 + (size_t)l * H_ * D_, qg_b2 + (size_t)l * D_,
                    out_qa + (size_t)l * BD, nullptr, D_, H_, ACT_NONE,
                    nullptr, nullptr, nullptr, nullptr);
    }

    // outputs
    finalize_kernel<<<4096, 256>>>(psum, emo, out, rcp);
    launch_gemm(rcp, cmat, nullptr, out_cf, nullptr, D_, D_, ACT_SIGMOID,
                nullptr, nullptr, nullptr, nullptr);
    stab_part_kernel<<<1024, 256>>>(psum, psq, part);
    stab_final_kernel<<<1, 256>>>(part, out_ss);
    (void)n_in; (void)out_size;
}

// round 7
// speedup vs baseline: 6.3521x; 1.2028x over previous
#include <cuda_runtime.h>
#include <cuda_fp16.h>
#include <math.h>
#include <stdint.h>

#define B_ 8192
#define D_ 1024
#define L_ 5
#define H_ 512
#define BD_ (B_ * D_)
#define NC_ 1536                              // merged es(1024)+qg1(512) width

// ================= scratch (device globals; no allocations) =================
__device__ __half g_cur[B_ * D_];
__device__ float  g_buf2d[B_ * 2 * D_];       // pre-LN float (pg1)
__device__ __half g_buf2dh[B_ * 2 * D_];      // GELU(LN) half
__device__ __half g_pat[B_ * D_];
__device__ float  g_tmpc[B_ * NC_];           // merged pre-LN float (es|qg1)
__device__ __half g_tmph[B_ * H_];            // ReLU(LN) half
__device__ float  g_emo[B_ * D_];
__device__ float  g_psum[B_ * D_];
__device__ float  g_psq[B_ * D_];
__device__ __half g_cmat[D_ * D_];            // C[k][n] = 0.9^((n-k)%D)
__device__ __half g_rcp[B_ * D_];
__device__ double g_part[1024];
__device__ float  g_bcomb[L_ * NC_];          // combined es_b | qg_b1
// half weights ([K,N] layout)
__device__ __half g_wpg1[L_ * D_ * 2 * D_];
__device__ __half g_wpg2[L_ * 2 * D_ * D_];
__device__ __half g_wcomb[L_ * D_ * NC_];     // es_w | qg_w1 merged
__device__ __half g_wqg2[L_ * H_ * D_];

enum { ACT_NONE = 0, ACT_TANH_STABLE = 1, ACT_SIGMOID = 2 };

// ================= helpers =================
__device__ __forceinline__ uint32_t smem_u32(const void* p) {
    uint32_t a;
    asm("{ .reg .u64 t; cvta.to.shared.u64 t, %1; cvt.u32.u64 %0, t; }"
        : "=r"(a) : "l"(p));
    return a;
}
__device__ __forceinline__ void cp16(uint32_t dst, const void* src) {
    asm volatile("cp.async.cg.shared.global [%0], [%1], 16;" :: "r"(dst), "l"(src));
}
__device__ __forceinline__ void cp_commit() {
    asm volatile("cp.async.commit_group;" ::: "memory");
}
template <int N>
__device__ __forceinline__ void cp_wait() {
    asm volatile("cp.async.wait_group %0;" :: "n"(N) : "memory");
}
__device__ __forceinline__ void ldm_x4(uint32_t* r, uint32_t addr) {
    asm volatile("ldmatrix.sync.aligned.m8n8.x4.shared.b16 {%0,%1,%2,%3}, [%4];"
                 : "=r"(r[0]), "=r"(r[1]), "=r"(r[2]), "=r"(r[3]) : "r"(addr));
}
__device__ __forceinline__ void ldm_x4_trans(uint32_t* r, uint32_t addr) {
    asm volatile("ldmatrix.sync.aligned.m8n8.x4.trans.shared.b16 {%0,%1,%2,%3}, [%4];"
                 : "=r"(r[0]), "=r"(r[1]), "=r"(r[2]), "=r"(r[3]) : "r"(addr));
}
__device__ __forceinline__ void mma_f16(float* d, const uint32_t* a, const uint32_t* b) {
    asm volatile(
        "mma.sync.aligned.m16n8k16.row.col.f32.f16.f16.f32 "
        "{%0,%1,%2,%3}, {%4,%5,%6,%7}, {%8,%9}, {%0,%1,%2,%3};"
        : "+f"(d[0]), "+f"(d[1]), "+f"(d[2]), "+f"(d[3])
        : "r"(a[0]), "r"(a[1]), "r"(a[2]), "r"(a[3]), "r"(b[0]), "r"(b[1]));
}
__device__ __forceinline__ float sigmf(float x) { return 1.f / (1.f + expf(-x)); }

// ================= fp16 tensor-core GEMM =================
#define MT 128
#define NT 128
#define KC 64
#define A_BYTES (MT * KC * 2)
#define B_BYTES (KC * NT * 2)
#define STAGE_BYTES (A_BYTES + B_BYTES)
#define GEMM_SMEM (2 * STAGE_BYTES)          // 65536 -> 2 CTAs/SM

__device__ __forceinline__ void copy_tiles(
    const __half* __restrict__ A, const __half* __restrict__ W, int N, int K,
    int rowBase, int colBase, int k0, uint32_t stageAddr, int tid)
{
#pragma unroll
    for (int j = 0; j < 4; j++) {
        int idx = tid + j * 256;
        int r = idx >> 3, c = idx & 7;
        const __half* src = A + (size_t)(rowBase + r) * K + k0 + c * 8;
        uint32_t off = (uint32_t)(r * 128 + c * 16);
        cp16(stageAddr + (off ^ ((off >> 3) & 0x70)), src);
    }
    const uint32_t bAddr = stageAddr + A_BYTES;
#pragma unroll
    for (int j = 0; j < 4; j++) {
        int idx = tid + j * 256;
        int kr = idx >> 4, c = idx & 15;
        const __half* src = W + (size_t)(k0 + kr) * N + colBase + c * 8;
        uint32_t off = (uint32_t)(kr * 256 + c * 16);
        cp16(bAddr + (off ^ ((off >> 4) & 0x70)), src);
    }
}

__global__ void __launch_bounds__(256, 2) mma_gemm(
    const __half* __restrict__ A, const __half* __restrict__ W,
    const float* __restrict__ bias, float* __restrict__ Cf, __half* __restrict__ Ch,
    int N, int K, int act, int init,
    const float* __restrict__ sc, __half* __restrict__ curout,
    float* __restrict__ psum, float* __restrict__ psq)
{
    extern __shared__ char smemraw[];
    const uint32_t sb = smem_u32(smemraw);
    const int tid = threadIdx.x;
    const int wid = tid >> 5, lane = tid & 31;
    const int g = lane >> 2, tig = lane & 3;
    const int warp_m = wid & 1;
    const int warp_n = wid >> 1;
    const int rowBase = blockIdx.y * MT;
    const int colBase = blockIdx.x * NT;
    const int nk = K / KC;

    const int lr = (lane & 7) + ((lane >> 3) & 1) * 8;
    const int lc16 = ((lane >> 4) & 1) * 16;

    float acc[4][4][4];
#pragma unroll
    for (int mi = 0; mi < 4; mi++)
#pragma unroll
        for (int ni = 0; ni < 4; ni++)
#pragma unroll
            for (int q = 0; q < 4; q++) acc[mi][ni][q] = 0.f;

    copy_tiles(A, W, N, K, rowBase, colBase, 0, sb, tid);
    cp_commit();

    const int arow0 = warp_m * 64;
    const int bcol0 = warp_n * 32;

    for (int i = 0; i < nk; i++) {
        if (i + 1 < nk) {
            copy_tiles(A, W, N, K, rowBase, colBase, (i + 1) * KC,
                       sb + (uint32_t)(((i + 1) & 1) * STAGE_BYTES), tid);
            cp_commit();
            cp_wait<1>();
        } else {
            cp_wait<0>();
        }
        __syncthreads();

        const uint32_t aBase = sb + (uint32_t)((i & 1) * STAGE_BYTES);
        const uint32_t bBase = aBase + A_BYTES;

#pragma unroll
        for (int ks = 0; ks < 4; ks++) {
            uint32_t af[4][4], bf[4][2];
#pragma unroll
            for (int mi = 0; mi < 4; mi++) {
                uint32_t off = (uint32_t)((arow0 + mi * 16 + lr) * 128 + ks * 32 + lc16);
                ldm_x4(af[mi], aBase + (off ^ ((off >> 3) & 0x70)));
            }
#pragma unroll
            for (int p = 0; p < 2; p++) {
                uint32_t off = (uint32_t)((ks * 16 + lr) * 256 +
                                          (bcol0 + p * 16) * 2 + lc16);
                uint32_t r[4];
                ldm_x4_trans(r, bBase + (off ^ ((off >> 4) & 0x70)));
                bf[2 * p][0] = r[0]; bf[2 * p][1] = r[1];
                bf[2 * p + 1][0] = r[2]; bf[2 * p + 1][1] = r[3];
            }
#pragma unroll
            for (int mi = 0; mi < 4; mi++)
#pragma unroll
                for (int ni = 0; ni < 4; ni++)
                    mma_f16(acc[mi][ni], af[mi], bf[ni]);
        }
        __syncthreads();
    }

    // ---------------- fused epilogue ----------------
    // anchors output (out + 3*BD + 1) is only 4B-aligned -> scalar path there
    const bool cf_vec = (((uintptr_t)Cf & 7) == 0);

#pragma unroll
    for (int mi = 0; mi < 4; mi++) {
        const int r0 = rowBase + warp_m * 64 + mi * 16 + g;
#pragma unroll
        for (int ni = 0; ni < 4; ni++) {
            const int c0 = colBase + warp_n * 32 + ni * 8 + tig * 2;
            float* a4 = acc[mi][ni];
            if (act == ACT_NONE) {
                const float b0 = bias[c0], b1 = bias[c0 + 1];
                if (cf_vec) {
                    *(float2*)(Cf + (size_t)r0 * N + c0) =
                        make_float2(a4[0] + b0, a4[1] + b1);
                    *(float2*)(Cf + (size_t)(r0 + 8) * N + c0) =
                        make_float2(a4[2] + b0, a4[3] + b1);
                } else {
                    Cf[(size_t)r0 * N + c0] = a4[0] + b0;
                    Cf[(size_t)r0 * N + c0 + 1] = a4[1] + b1;
                    Cf[(size_t)(r0 + 8) * N + c0] = a4[2] + b0;
                    Cf[(size_t)(r0 + 8) * N + c0 + 1] = a4[3] + b1;
                }
            } else if (act == ACT_SIGMOID) {
                *(float2*)(Cf + (size_t)r0 * N + c0) =
                    make_float2(sigmf(a4[0]), sigmf(a4[1]));
                *(float2*)(Cf + (size_t)(r0 + 8) * N + c0) =
                    make_float2(sigmf(a4[2]), sigmf(a4[3]));
            } else {  // ACT_TANH_STABLE
                const float b0 = bias[c0], b1 = bias[c0 + 1];
                const float g0 = sigmf(sc[c0]), g1 = sigmf(sc[c0 + 1]);
#pragma unroll
                for (int h = 0; h < 2; h++) {
                    const int row = r0 + h * 8;
                    const size_t idx = (size_t)row * N + c0;
                    float p0 = tanhf(a4[2 * h] + b0);
                    float p1 = tanhf(a4[2 * h + 1] + b1);
                    float s0 = p0 * g0, s1 = p1 * g1;
                    *(__half2*)(Ch + idx) = __floats2half2_rn(p0, p1);
                    *(__half2*)(curout + idx) = __floats2half2_rn(s0, s1);
                    if (init) {
                        *(float2*)(psum + idx) = make_float2(s0, s1);
                        *(float2*)(psq + idx) = make_float2(s0 * s0, s1 * s1);
                    } else {
                        float2 u = *(float2*)(psum + idx);
                        *(float2*)(psum + idx) = make_float2(u.x + s0, u.y + s1);
                        float2 v = *(float2*)(psq + idx);
                        *(float2*)(psq + idx) = make_float2(v.x + s0 * s0, v.y + s1 * s1);
                    }
                }
            }
        }
    }
}

// ================= LayerNorm + activation (vectorized) =================
// act: 0 = GELU->half out, 1 = sigmoid->float accum (+= or init), 2 = ReLU->half out
__global__ void __launch_bounds__(128) ln_act_kernel(
    const float* __restrict__ in, int stride, int off,
    const float* __restrict__ g, const float* __restrict__ be,
    __half* __restrict__ outh, float* __restrict__ accum,
    int N, int act, int init)
{
    const int row = blockIdx.x;
    const float4* x = (const float4*)(in + (size_t)row * stride + off);
    const int nv = N >> 9;               // float4s per thread: 2048->4,1024->2,512->1
    float4 v[4];
    float s = 0.f, ss = 0.f;
    for (int t = 0; t < nv; t++) {
        float4 w = x[threadIdx.x + (t << 7)];
        v[t] = w;
        s += w.x + w.y + w.z + w.w;
        ss += w.x * w.x + w.y * w.y + w.z * w.z + w.w * w.w;
    }
#pragma unroll
    for (int o = 16; o > 0; o >>= 1) {
        s += __shfl_down_sync(0xffffffff, s, o);
        ss += __shfl_down_sync(0xffffffff, ss, o);
    }
    __shared__ float sm[8];
    __shared__ float s_mean, s_rstd;
    const int w4 = threadIdx.x >> 5, lane = threadIdx.x & 31;
    if (lane == 0) { sm[w4] = s; sm[4 + w4] = ss; }
    __syncthreads();
    if (threadIdx.x == 0) {
        float S = sm[0] + sm[1] + sm[2] + sm[3];
        float SS = sm[4] + sm[5] + sm[6] + sm[7];
        float m = S / (float)N;
        s_mean = m;
        s_rstd = rsqrtf(SS / (float)N - m * m + 1e-5f);
    }
    __syncthreads();
    const float m = s_mean, r = s_rstd;
    for (int t = 0; t < nv; t++) {
        const int c = (threadIdx.x + (t << 7)) << 2;
        float4 gg = *(const float4*)(g + c);
        float4 bb = *(const float4*)(be + c);
        float o0 = (v[t].x - m) * r * gg.x + bb.x;
        float o1 = (v[t].y - m) * r * gg.y + bb.y;
        float o2 = (v[t].z - m) * r * gg.z + bb.z;
        float o3 = (v[t].w - m) * r * gg.w + bb.w;
        const size_t idx = (size_t)row * N + c;
        if (act == 0) {
            const float k = 0.70710678118654752f;
            o0 = 0.5f * o0 * (1.f + erff(o0 * k));
            o1 = 0.5f * o1 * (1.f + erff(o1 * k));
            o2 = 0.5f * o2 * (1.f + erff(o2 * k));
            o3 = 0.5f * o3 * (1.f + erff(o3 * k));
            *(__half2*)(outh + idx) = __floats2half2_rn(o0, o1);
            *(__half2*)(outh + idx + 2) = __floats2half2_rn(o2, o3);
        } else if (act == 1) {
            float4 a;
            a.x = sigmf(o0); a.y = sigmf(o1); a.z = sigmf(o2); a.w = sigmf(o3);
            if (!init) {
                float4 p = *(float4*)(accum + idx);
                a.x += p.x; a.y += p.y; a.z += p.z; a.w += p.w;
            }
            *(float4*)(accum + idx) = a;
        } else {
            o0 = fmaxf(o0, 0.f); o1 = fmaxf(o1, 0.f);
            o2 = fmaxf(o2, 0.f); o3 = fmaxf(o3, 0.f);
            *(__half2*)(outh + idx) = __floats2half2_rn(o0, o1);
            *(__half2*)(outh + idx + 2) = __floats2half2_rn(o2, o3);
        }
    }
}

// ================= small kernels (vectorized) =================
__global__ void __launch_bounds__(256) h_copy_kernel(const float4* __restrict__ in,
                                                     __half* __restrict__ out, int n4) {
    for (int i = blockIdx.x * 256 + threadIdx.x; i < n4; i += gridDim.x * 256) {
        float4 v = in[i];
        *(__half2*)(out + 4 * (size_t)i) = __floats2half2_rn(v.x, v.y);
        *(__half2*)(out + 4 * (size_t)i + 2) = __floats2half2_rn(v.z, v.w);
    }
}

// weight conversion: pg_w1, pg_w2, qg_w2 direct; es_w+qg_w1 merged into comb
__global__ void __launch_bounds__(256) wround_kernel(
    const float4* s1, __half* d1, int n1v,
    const float4* s2, __half* d2, int n2v,
    const float* __restrict__ esw, const float* __restrict__ qgw1,
    __half* __restrict__ comb,
    const float4* s5, __half* d5, int n5v)
{
    const int stride = gridDim.x * 256;
    const int t0 = blockIdx.x * 256 + threadIdx.x;
    for (int i = t0; i < n1v; i += stride) {
        float4 v = s1[i];
        *(__half2*)(d1 + 4 * (size_t)i) = __floats2half2_rn(v.x, v.y);
        *(__half2*)(d1 + 4 * (size_t)i + 2) = __floats2half2_rn(v.z, v.w);
    }
    for (int i = t0; i < n2v; i += stride) {
        float4 v = s2[i];
        *(__half2*)(d2 + 4 * (size_t)i) = __floats2half2_rn(v.x, v.y);
        *(__half2*)(d2 + 4 * (size_t)i + 2) = __floats2half2_rn(v.z, v.w);
    }
    for (int i = t0; i < n5v; i += stride) {
        float4 v = s5[i];
        *(__half2*)(d5 + 4 * (size_t)i) = __floats2half2_rn(v.x, v.y);
        *(__half2*)(d5 + 4 * (size_t)i + 2) = __floats2half2_rn(v.z, v.w);
    }
    // merged: comb[(l*D+k)*1536 + n] = n<1024 ? esw[(l*D+k)*1024+n] : qgw1[(l*D+k)*512+n-1024]
    const int ncomb4 = L_ * D_ * (NC_ / 4);
    for (int i = t0; i < ncomb4; i += stride) {
        int lk = i / (NC_ / 4);
        int n = (i % (NC_ / 4)) << 2;
        float4 v;
        if (n < 1024)
            v = *(const float4*)(esw + (size_t)lk * 1024 + n);
        else
            v = *(const float4*)(qgw1 + (size_t)lk * 512 + (n - 1024));
        __half* dst = comb + (size_t)lk * NC_ + n;
        *(__half2*)dst = __floats2half2_rn(v.x, v.y);
        *(__half2*)(dst + 2) = __floats2half2_rn(v.z, v.w);
    }
}

// cmat init + combined bias
__global__ void __launch_bounds__(256) cinit_kernel(__half* C, float* bcomb,
                                                    const float* esb, const float* qgb1) {
    int idx = blockIdx.x * 256 + threadIdx.x;
    int k = idx >> 10;
    int n = idx & (D_ - 1);
    int e = (n - k + D_) & (D_ - 1);
    C[idx] = __float2half_rn(powf(0.9f, (float)e));
    if (idx < L_ * NC_) {
        int l = idx / NC_, c = idx % NC_;
        bcomb[idx] = (c < 1024) ? esb[l * 1024 + c] : qgb1[l * 512 + (c - 1024)];
    }
}

__global__ void __launch_bounds__(256) finalize_kernel(
    const float4* __restrict__ ps, const float4* __restrict__ es,
    float* __restrict__ out, __half* __restrict__ rcp) {
    for (int i = blockIdx.x * 256 + threadIdx.x; i < BD_ / 4; i += gridDim.x * 256) {
        float4 p = ps[i], e = es[i];
        float4 cp = make_float4(p.x * 0.2f, p.y * 0.2f, p.z * 0.2f, p.w * 0.2f);
        *(float4*)(out + 4 * (size_t)i) = cp;
        *(float4*)(out + (size_t)BD_ + 4 * (size_t)i) =
            make_float4(e.x * 0.2f, e.y * 0.2f, e.z * 0.2f, e.w * 0.2f);
        *(__half2*)(rcp + 4 * (size_t)i) = __floats2half2_rn(cp.x, cp.y);
        *(__half2*)(rcp + 4 * (size_t)i + 2) = __floats2half2_rn(cp.z, cp.w);
    }
}

__global__ void __launch_bounds__(256) stab_part_kernel(
    const float4* __restrict__ ps, const float4* __restrict__ psq,
    double* __restrict__ part) {
    double acc = 0.0;
    for (int i = blockIdx.x * 256 + threadIdx.x; i < BD_ / 4; i += gridDim.x * 256) {
        float4 s = ps[i], q = psq[i];
        acc += (double)((q.x - s.x * s.x * 0.2f) * 0.25f);
        acc += (double)((q.y - s.y * s.y * 0.2f) * 0.25f);
        acc += (double)((q.z - s.z * s.z * 0.2f) * 0.25f);
        acc += (double)((q.w - s.w * s.w * 0.2f) * 0.25f);
    }
#pragma unroll
    for (int o = 16; o > 0; o >>= 1)
        acc += __shfl_down_sync(0xffffffff, acc, o);
    __shared__ double sm[8];
    int w = threadIdx.x >> 5, lane = threadIdx.x & 31;
    if (lane == 0) sm[w] = acc;
    __syncthreads();
    if (threadIdx.x == 0) {
        double t = 0.0;
        for (int i = 0; i < 8; i++) t += sm[i];
        part[blockIdx.x] = t;
    }
}

__global__ void __launch_bounds__(256) stab_final_kernel(const double* __restrict__ part,
                                                         float* __restrict__ out) {
    double acc = 0.0;
    for (int i = threadIdx.x; i < 1024; i += 256) acc += part[i];
#pragma unroll
    for (int o = 16; o > 0; o >>= 1)
        acc += __shfl_down_sync(0xffffffff, acc, o);
    __shared__ double sm[8];
    int w = threadIdx.x >> 5, lane = threadIdx.x & 31;
    if (lane == 0) sm[w] = acc;
    __syncthreads();
    if (threadIdx.x == 0) {
        double t = 0.0;
        for (int i = 0; i < 8; i++) t += sm[i];
        out[0] = (float)(1.0 - t / (double)BD_);
    }
}

// ================= host launch =================
static inline void launch_gemm(const __half* A, const __half* W, const float* bias,
                               float* Cf, __half* Ch, int N, int K, int act, int init,
                               const float* sc, __half* curout, float* psum, float* psq) {
    dim3 grid(N / NT, B_ / MT);
    mma_gemm<<<grid, 256, GEMM_SMEM>>>(A, W, bias, Cf, Ch, N, K, act, init,
                                       sc, curout, psum, psq);
}

extern "C" void kernel_launch(void* const* d_in, const int* in_sizes, int n_in,
                              void* d_out, int out_size)
{
    const float* seed = (const float*)d_in[0];
    const int o = (in_sizes[1] == 1) ? 2 : 1;
    const float* pg_w1 = (const float*)d_in[o + 0];
    const float* pg_b1 = (const float*)d_in[o + 1];
    const float* pg_g1 = (const float*)d_in[o + 2];
    const float* pg_be1 = (const float*)d_in[o + 3];
    const float* pg_w2 = (const float*)d_in[o + 4];
    const float* pg_b2 = (const float*)d_in[o + 5];
    const float* es_w = (const float*)d_in[o + 6];
    const float* es_b = (const float*)d_in[o + 7];
    const float* es_g = (const float*)d_in[o + 8];
    const float* es_be = (const float*)d_in[o + 9];
    const float* qg_w1 = (const float*)d_in[o + 10];
    const float* qg_b1 = (const float*)d_in[o + 11];
    const float* qg_g1 = (const float*)d_in[o + 12];
    const float* qg_be1 = (const float*)d_in[o + 13];
    const float* qg_w2 = (const float*)d_in[o + 14];
    const float* qg_b2 = (const float*)d_in[o + 15];
    const float* sc = (const float*)d_in[o + 16];
    float* out = (float*)d_out;

    __half *cur, *buf2dh, *pat, *tmph, *cmat, *rcp;
    __half *wpg1, *wpg2, *wcomb, *wqg2;
    float *buf2d, *tmpc, *emo, *psum, *psq, *bcomb;
    double* part;
    cudaGetSymbolAddress((void**)&cur, g_cur);
    cudaGetSymbolAddress((void**)&buf2d, g_buf2d);
    cudaGetSymbolAddress((void**)&buf2dh, g_buf2dh);
    cudaGetSymbolAddress((void**)&pat, g_pat);
    cudaGetSymbolAddress((void**)&tmpc, g_tmpc);
    cudaGetSymbolAddress((void**)&tmph, g_tmph);
    cudaGetSymbolAddress((void**)&emo, g_emo);
    cudaGetSymbolAddress((void**)&psum, g_psum);
    cudaGetSymbolAddress((void**)&psq, g_psq);
    cudaGetSymbolAddress((void**)&cmat, g_cmat);
    cudaGetSymbolAddress((void**)&rcp, g_rcp);
    cudaGetSymbolAddress((void**)&part, g_part);
    cudaGetSymbolAddress((void**)&bcomb, g_bcomb);
    cudaGetSymbolAddress((void**)&wpg1, g_wpg1);
    cudaGetSymbolAddress((void**)&wpg2, g_wpg2);
    cudaGetSymbolAddress((void**)&wcomb, g_wcomb);
    cudaGetSymbolAddress((void**)&wqg2, g_wqg2);

    cudaFuncSetAttribute(mma_gemm, cudaFuncAttributeMaxDynamicSharedMemorySize, GEMM_SMEM);

    const size_t BD = (size_t)BD_;
    float* out_cf = out + 2 * BD;
    float* out_ss = out + 3 * BD;
    float* out_qa = out + 3 * BD + 1;

    h_copy_kernel<<<2048, 256>>>((const float4*)seed, cur, BD_ / 4);
    cinit_kernel<<<(D_ * D_) / 256, 256>>>(cmat, bcomb, es_b, qg_b1);
    wround_kernel<<<4096, 256>>>(
        (const float4*)pg_w1, wpg1, L_ * D_ * 2 * D_ / 4,
        (const float4*)pg_w2, wpg2, L_ * 2 * D_ * D_ / 4,
        es_w, qg_w1, wcomb,
        (const float4*)qg_w2, wqg2, L_ * H_ * D_ / 4);

    for (int l = 0; l < L_; l++) {
        // 1) pre1 = cur @ pg_w1 + b1   [B,2D] float
        launch_gemm(cur, wpg1 + (size_t)l * D_ * 2 * D_, pg_b1 + (size_t)l * 2 * D_,
                    buf2d, nullptr, 2 * D_, D_, ACT_NONE, 0,
                    nullptr, nullptr, nullptr, nullptr);
        // 2) h = GELU(LN(pre1)) -> half
        ln_act_kernel<<<B_, 128>>>(buf2d, 2 * D_, 0, pg_g1 + (size_t)l * 2 * D_,
                                   pg_be1 + (size_t)l * 2 * D_, buf2dh, nullptr,
                                   2 * D_, 0, 0);
        // 3) pat = tanh(h @ pg_w2 + b2); fused stable/cur/psum/psq (init on l==0)
        launch_gemm(buf2dh, wpg2 + (size_t)l * 2 * D_ * D_, pg_b2 + (size_t)l * D_,
                    nullptr, pat, D_, 2 * D_, ACT_TANH_STABLE, (l == 0),
                    sc + (size_t)l * D_, cur, psum, psq);
        // 4+6 merged) tmpc = pat @ [es_w|qg_w1] + [es_b|qg_b1]   [B,1536] float
        launch_gemm(pat, wcomb + (size_t)l * D_ * NC_, bcomb + (size_t)l * NC_,
                    tmpc, nullptr, NC_, D_, ACT_NONE, 0,
                    nullptr, nullptr, nullptr, nullptr);
        // 5) emo (init/+=) = sigmoid(LN(tmpc[:, :1024]))
        ln_act_kernel<<<B_, 128>>>(tmpc, NC_, 0, es_g + (size_t)l * D_,
                                   es_be + (size_t)l * D_, nullptr, emo,
                                   D_, 1, (l == 0));
        // 7) tmph = ReLU(LN(tmpc[:, 1024:1536])) -> half
        ln_act_kernel<<<B_, 128>>>(tmpc, NC_, 1024, qg_g1 + (size_t)l * H_,
                                   qg_be1 + (size_t)l * H_, tmph, nullptr,
                                   H_, 2, 0);
        // 8) anchors[l] = tmph @ qg_w2 + qg_b2 -> d_out (float, scalar stores)
        launch_gemm(tmph, wqg2 + (size_t)l * H_ * D_, qg_b2 + (size_t)l * D_,
                    out_qa + (size_t)l * BD, nullptr, D_, H_, ACT_NONE, 0,
                    nullptr, nullptr, nullptr, nullptr);
    }

    finalize_kernel<<<2048, 256>>>((const float4*)psum, (const float4*)emo, out, rcp);
    launch_gemm(rcp, cmat, nullptr, out_cf, nullptr, D_, D_, ACT_SIGMOID, 0,
                nullptr, nullptr, nullptr, nullptr);
    stab_part_kernel<<<1024, 256>>>((const float4*)psum, (const float4*)psq, part);
    stab_final_kernel<<<1, 256>>>(part, out_ss);
    (void)n_in; (void)out_size;
}